// round 2
// baseline (speedup 1.0000x reference)
#include <cuda_runtime.h>
#include <math.h>

#define Nn 50000
#define Ee 800000
#define ET (Ee + Nn)
#define Hh 4
#define Ff 128
#define NEG 0.2f
#define BN_EPS 1e-5f

// ---------------- scratch (device globals; no allocation allowed) ----------
__device__ __align__(16) float g_h[(size_t)Nn * Ff];     // projected features [N,128]
__device__ __align__(16) float g_asrc[Nn * Hh];          // per-node src attention logits
__device__ __align__(16) float g_adst[Nn * Hh];          // per-node dst attention logits
__device__ __align__(16) float g_ex[(size_t)ET * Hh];    // exp(e) per edge per head
__device__ float g_den[Nn * Hh];                          // softmax denominators
__device__ __align__(16) float g_agg[(size_t)Nn * Ff];   // aggregated output
__device__ float g_bns[Ff];                               // BN sum per feature
__device__ float g_bnq[Ff];                               // BN sumsq per feature

// ---------------- K1: h = x @ W^T  (tiled fp32 SGEMM) ----------------------
// Block: 64 rows x 128 cols, 256 threads, each thread 4x8 register tile.
__global__ void gemm_kernel(const float* __restrict__ x, const float* __restrict__ W) {
    __shared__ float xs[64 * 33];
    __shared__ float wt[32 * 132];
    int tid = threadIdx.x;
    int row0 = blockIdx.x * 64;
    int cg = tid & 15;   // col group: cols cg*8 .. cg*8+7
    int rg = tid >> 4;   // row group: rows rg*4 .. rg*4+3

    float acc[4][8];
#pragma unroll
    for (int i = 0; i < 4; i++)
#pragma unroll
        for (int j = 0; j < 8; j++) acc[i][j] = 0.f;

    for (int kb = 0; kb < 128; kb += 32) {
        // stage x tile [64 x 32]
#pragma unroll
        for (int i = 0; i < 8; i++) {
            int lin = i * 256 + tid;
            int r = lin >> 5, k = lin & 31;
            int gr = row0 + r;
            xs[r * 33 + k] = (gr < Nn) ? x[(size_t)gr * 128 + kb + k] : 0.f;
        }
        // stage W chunk transposed: wt[k][f]
#pragma unroll
        for (int i = 0; i < 16; i++) {
            int lin = i * 256 + tid;
            int f = lin >> 5, k = lin & 31;
            wt[k * 132 + f] = W[f * 128 + kb + k];
        }
        __syncthreads();
#pragma unroll
        for (int k = 0; k < 32; k++) {
            float xv[4];
#pragma unroll
            for (int i = 0; i < 4; i++) xv[i] = xs[(rg * 4 + i) * 33 + k];
            float4 w0 = *(float4*)&wt[k * 132 + cg * 8];
            float4 w1 = *(float4*)&wt[k * 132 + cg * 8 + 4];
#pragma unroll
            for (int i = 0; i < 4; i++) {
                acc[i][0] += xv[i] * w0.x; acc[i][1] += xv[i] * w0.y;
                acc[i][2] += xv[i] * w0.z; acc[i][3] += xv[i] * w0.w;
                acc[i][4] += xv[i] * w1.x; acc[i][5] += xv[i] * w1.y;
                acc[i][6] += xv[i] * w1.z; acc[i][7] += xv[i] * w1.w;
            }
        }
        __syncthreads();
    }
#pragma unroll
    for (int i = 0; i < 4; i++) {
        int gr = row0 + rg * 4 + i;
        if (gr < Nn) {
            float4 v0 = make_float4(acc[i][0], acc[i][1], acc[i][2], acc[i][3]);
            float4 v1 = make_float4(acc[i][4], acc[i][5], acc[i][6], acc[i][7]);
            *(float4*)&g_h[(size_t)gr * 128 + cg * 8] = v0;
            *(float4*)&g_h[(size_t)gr * 128 + cg * 8 + 4] = v1;
        }
    }
}

// ---------------- K2: per-node attention logits ----------------------------
// One warp per node: a_src[n,h] = dot(h[n,h,:], att_src[h,:]); same for dst.
__global__ void att_kernel(const float* __restrict__ att_src,
                           const float* __restrict__ att_dst) {
    int w = (blockIdx.x * blockDim.x + threadIdx.x) >> 5;
    int lane = threadIdx.x & 31;
    if (w >= Nn) return;
    const float* hr = &g_h[(size_t)w * 128];
#pragma unroll
    for (int hd = 0; hd < Hh; hd++) {
        float v = hr[hd * 32 + lane];
        float s = v * att_src[hd * 32 + lane];
        float d = v * att_dst[hd * 32 + lane];
#pragma unroll
        for (int o = 16; o > 0; o >>= 1) {
            s += __shfl_down_sync(0xFFFFFFFFu, s, o);
            d += __shfl_down_sync(0xFFFFFFFFu, d, o);
        }
        if (lane == 0) {
            g_asrc[w * 4 + hd] = s;
            g_adst[w * 4 + hd] = d;
        }
    }
}

// ---------------- K3: edge pass A: exp(leaky_relu(e)) + denom atomics ------
// edge_index is int32 (JAX default config downcasts int64 -> int32).
__global__ void edgeA_kernel(const int* __restrict__ ei) {
    int i = blockIdx.x * blockDim.x + threadIdx.x;
    if (i >= ET) return;
    int s, d;
    if (i < Ee) { s = ei[i]; d = ei[Ee + i]; }
    else        { s = d = i - Ee; }
    float4 as = *(const float4*)&g_asrc[s * 4];
    float4 ad = *(const float4*)&g_adst[d * 4];
    float e0 = as.x + ad.x, e1 = as.y + ad.y, e2 = as.z + ad.z, e3 = as.w + ad.w;
    e0 = e0 > 0.f ? e0 : NEG * e0;
    e1 = e1 > 0.f ? e1 : NEG * e1;
    e2 = e2 > 0.f ? e2 : NEG * e2;
    e3 = e3 > 0.f ? e3 : NEG * e3;
    // No max-subtraction needed: |e| is small (sigma ~0.8), exp cannot overflow,
    // and alpha = exp(e)/sum exp(e) is identical to the max-shifted form.
    float x0 = __expf(e0), x1 = __expf(e1), x2 = __expf(e2), x3 = __expf(e3);
    *(float4*)&g_ex[(size_t)i * 4] = make_float4(x0, x1, x2, x3);
    atomicAdd(&g_den[d * 4 + 0], x0);
    atomicAdd(&g_den[d * 4 + 1], x1);
    atomicAdd(&g_den[d * 4 + 2], x2);
    atomicAdd(&g_den[d * 4 + 3], x3);
}

// ---------------- K4: edge pass B: weighted scatter-aggregate --------------
// One warp per edge. Lane l handles features [4l, 4l+3] (all in head l/8).
__global__ void edgeB_kernel(const int* __restrict__ ei) {
    int w = (blockIdx.x * blockDim.x + threadIdx.x) >> 5;
    int lane = threadIdx.x & 31;
    if (w >= ET) return;
    int s, d;
    if (w < Ee) { s = ei[w]; d = ei[Ee + w]; }
    else        { s = d = w - Ee; }
    int hd = lane >> 3;
    float ex = g_ex[(size_t)w * 4 + hd];
    float den = g_den[d * 4 + hd];
    float al = ex / (den + 1e-16f);
    float4 hv = ((const float4*)g_h)[(size_t)s * 32 + lane];
    hv.x *= al; hv.y *= al; hv.z *= al; hv.w *= al;
    float4* p = &((float4*)g_agg)[(size_t)d * 32 + lane];
    asm volatile("red.global.add.v4.f32 [%0], {%1,%2,%3,%4};"
                 :: "l"(p), "f"(hv.x), "f"(hv.y), "f"(hv.z), "f"(hv.w)
                 : "memory");
}

// ---------------- K5: bias + relu + BN partial sums ------------------------
__global__ void bn_reduce_kernel(const float* __restrict__ bias) {
    int f = threadIdx.x;  // 128 threads = 128 features
    float b = bias[f];
    float s = 0.f, q = 0.f;
    for (int n = blockIdx.x; n < Nn; n += gridDim.x) {
        float v = g_agg[(size_t)n * 128 + f] + b;
        v = v > 0.f ? v : 0.f;
        g_agg[(size_t)n * 128 + f] = v;
        s += v;
        q += v * v;
    }
    atomicAdd(&g_bns[f], s);
    atomicAdd(&g_bnq[f], q);
}

// ---------------- K6: BN normalize + write output --------------------------
__global__ void bn_apply_kernel(const float* __restrict__ gamma,
                                const float* __restrict__ beta,
                                float* __restrict__ out) {
    int i = blockIdx.x * blockDim.x + threadIdx.x;
    if (i >= Nn * 128) return;
    int f = i & 127;
    const float invn = 1.f / (float)Nn;
    float mean = g_bns[f] * invn;
    float var = g_bnq[f] * invn - mean * mean;
    out[i] = (g_agg[i] - mean) * rsqrtf(var + BN_EPS) * gamma[f] + beta[f];
}

// ---------------- launch ---------------------------------------------------
extern "C" void kernel_launch(void* const* d_in, const int* in_sizes, int n_in,
                              void* d_out, int out_size) {
    (void)in_sizes; (void)n_in; (void)out_size;
    const float* x        = (const float*)d_in[0];
    const int*   ei       = (const int*)d_in[1];   // int32 edge indices
    const float* W        = (const float*)d_in[2];
    const float* att_src  = (const float*)d_in[3];
    const float* att_dst  = (const float*)d_in[4];
    const float* bias     = (const float*)d_in[5];
    const float* gamma    = (const float*)d_in[6];
    const float* beta     = (const float*)d_in[7];

    void* p;
    cudaGetSymbolAddress(&p, g_den);
    cudaMemsetAsync(p, 0, sizeof(float) * Nn * Hh);
    cudaGetSymbolAddress(&p, g_agg);
    cudaMemsetAsync(p, 0, sizeof(float) * (size_t)Nn * Ff);
    cudaGetSymbolAddress(&p, g_bns);
    cudaMemsetAsync(p, 0, sizeof(float) * Ff);
    cudaGetSymbolAddress(&p, g_bnq);
    cudaMemsetAsync(p, 0, sizeof(float) * Ff);

    gemm_kernel<<<(Nn + 63) / 64, 256>>>(x, W);
    att_kernel<<<(Nn * 32 + 255) / 256, 256>>>(att_src, att_dst);
    edgeA_kernel<<<(ET + 255) / 256, 256>>>(ei);
    edgeB_kernel<<<(ET + 7) / 8, 256>>>(ei);          // 8 warps/block, warp per edge
    bn_reduce_kernel<<<592, 128>>>(bias);
    bn_apply_kernel<<<(Nn * 128 + 255) / 256, 256>>>(gamma, beta, (float*)d_out);
}

// round 3
// speedup vs baseline: 1.3426x; 1.3426x over previous
#include <cuda_runtime.h>
#include <math.h>

#define Nn 50000
#define Ee 800000
#define Hh 4
#define Ff 128
#define NEG 0.2f
#define BN_EPS 1e-5f
#define NB 196            // ceil(50000/256) scan blocks

// ---------------- scratch (device globals) ----------------------------------
__device__ __align__(16) float g_h[(size_t)Nn * Ff];     // projected features [N,128]
__device__ __align__(16) float g_asrc[Nn * Hh];          // per-node src attention logits
__device__ __align__(16) float g_adst[Nn * Hh];          // per-node dst attention logits
__device__ __align__(16) float g_agg[(size_t)Nn * Ff];   // aggregated (pre-BN) output
__device__ int   g_cnt[Nn];                               // in-degree (no self loop)
__device__ int   g_cur[Nn];                               // scatter cursor
__device__ int   g_row[Nn];                               // CSR row starts
__device__ int   g_bsum[NB];                              // scan block sums
__device__ int   g_boff[NB];                              // scanned block offsets
__device__ int   g_csr[Ee];                               // src node per CSR slot
__device__ float g_bns[Ff];                               // BN sum per feature
__device__ float g_bnq[Ff];                               // BN sumsq per feature

// ---------------- K1: h = x @ W^T  (tiled fp32 SGEMM) -----------------------
__global__ void gemm_kernel(const float* __restrict__ x, const float* __restrict__ W) {
    __shared__ float xs[64 * 33];
    __shared__ float wt[32 * 132];
    int tid = threadIdx.x;
    int row0 = blockIdx.x * 64;
    int cg = tid & 15;
    int rg = tid >> 4;

    float acc[4][8];
#pragma unroll
    for (int i = 0; i < 4; i++)
#pragma unroll
        for (int j = 0; j < 8; j++) acc[i][j] = 0.f;

    for (int kb = 0; kb < 128; kb += 32) {
#pragma unroll
        for (int i = 0; i < 8; i++) {
            int lin = i * 256 + tid;
            int r = lin >> 5, k = lin & 31;
            int gr = row0 + r;
            xs[r * 33 + k] = (gr < Nn) ? x[(size_t)gr * 128 + kb + k] : 0.f;
        }
#pragma unroll
        for (int i = 0; i < 16; i++) {
            int lin = i * 256 + tid;
            int f = lin >> 5, k = lin & 31;
            wt[k * 132 + f] = W[f * 128 + kb + k];
        }
        __syncthreads();
#pragma unroll
        for (int k = 0; k < 32; k++) {
            float xv[4];
#pragma unroll
            for (int i = 0; i < 4; i++) xv[i] = xs[(rg * 4 + i) * 33 + k];
            float4 w0 = *(float4*)&wt[k * 132 + cg * 8];
            float4 w1 = *(float4*)&wt[k * 132 + cg * 8 + 4];
#pragma unroll
            for (int i = 0; i < 4; i++) {
                acc[i][0] += xv[i] * w0.x; acc[i][1] += xv[i] * w0.y;
                acc[i][2] += xv[i] * w0.z; acc[i][3] += xv[i] * w0.w;
                acc[i][4] += xv[i] * w1.x; acc[i][5] += xv[i] * w1.y;
                acc[i][6] += xv[i] * w1.z; acc[i][7] += xv[i] * w1.w;
            }
        }
        __syncthreads();
    }
#pragma unroll
    for (int i = 0; i < 4; i++) {
        int gr = row0 + rg * 4 + i;
        if (gr < Nn) {
            *(float4*)&g_h[(size_t)gr * 128 + cg * 8] =
                make_float4(acc[i][0], acc[i][1], acc[i][2], acc[i][3]);
            *(float4*)&g_h[(size_t)gr * 128 + cg * 8 + 4] =
                make_float4(acc[i][4], acc[i][5], acc[i][6], acc[i][7]);
        }
    }
}

// ---------------- K2: per-node attention logits ------------------------------
__global__ void att_kernel(const float* __restrict__ att_src,
                           const float* __restrict__ att_dst) {
    int w = (blockIdx.x * blockDim.x + threadIdx.x) >> 5;
    int lane = threadIdx.x & 31;
    if (w >= Nn) return;
    const float* hr = &g_h[(size_t)w * 128];
#pragma unroll
    for (int hd = 0; hd < Hh; hd++) {
        float v = hr[hd * 32 + lane];
        float s = v * att_src[hd * 32 + lane];
        float d = v * att_dst[hd * 32 + lane];
#pragma unroll
        for (int o = 16; o > 0; o >>= 1) {
            s += __shfl_down_sync(0xFFFFFFFFu, s, o);
            d += __shfl_down_sync(0xFFFFFFFFu, d, o);
        }
        if (lane == 0) {
            g_asrc[w * 4 + hd] = s;
            g_adst[w * 4 + hd] = d;
        }
    }
}

// ---------------- CSR build: histogram / scan / scatter ----------------------
__global__ void hist_kernel(const int* __restrict__ ei) {
    int i = blockIdx.x * blockDim.x + threadIdx.x;
    if (i >= Ee) return;
    atomicAdd(&g_cnt[ei[Ee + i]], 1);
}

// block-local exclusive scan (256/block), emits block sum
__global__ void scan1_kernel() {
    int i = blockIdx.x * 256 + threadIdx.x;
    int lane = threadIdx.x & 31, wid = threadIdx.x >> 5;
    int v = (i < Nn) ? g_cnt[i] : 0;
    int x = v;
#pragma unroll
    for (int o = 1; o < 32; o <<= 1) {
        int y = __shfl_up_sync(0xFFFFFFFFu, x, o);
        if (lane >= o) x += y;
    }
    __shared__ int wsum[8];
    if (lane == 31) wsum[wid] = x;
    __syncthreads();
    if (wid == 0 && lane < 8) {
        int t = wsum[lane];
        int xx = t;
#pragma unroll
        for (int o = 1; o < 8; o <<= 1) {
            int y = __shfl_up_sync(0xFFu, xx, o);
            if (lane >= o) xx += y;
        }
        wsum[lane] = xx - t;   // exclusive warp offsets
    }
    __syncthreads();
    int incl = x + wsum[wid];
    if (i < Nn) g_row[i] = incl - v;
    if (threadIdx.x == 255) g_bsum[blockIdx.x] = incl;
}

__global__ void scan2_kernel() {
    int lane = threadIdx.x & 31, wid = threadIdx.x >> 5;
    int v = (threadIdx.x < NB) ? g_bsum[threadIdx.x] : 0;
    int x = v;
#pragma unroll
    for (int o = 1; o < 32; o <<= 1) {
        int y = __shfl_up_sync(0xFFFFFFFFu, x, o);
        if (lane >= o) x += y;
    }
    __shared__ int wsum[8];
    if (lane == 31) wsum[wid] = x;
    __syncthreads();
    if (wid == 0 && lane < 8) {
        int t = wsum[lane];
        int xx = t;
#pragma unroll
        for (int o = 1; o < 8; o <<= 1) {
            int y = __shfl_up_sync(0xFFu, xx, o);
            if (lane >= o) xx += y;
        }
        wsum[lane] = xx - t;
    }
    __syncthreads();
    if (threadIdx.x < NB) g_boff[threadIdx.x] = x + wsum[wid] - v;
}

__global__ void scan3_kernel() {
    int i = blockIdx.x * 256 + threadIdx.x;
    if (i < Nn) g_row[i] += g_boff[blockIdx.x];
}

__global__ void scatter_kernel(const int* __restrict__ ei) {
    int i = blockIdx.x * blockDim.x + threadIdx.x;
    if (i >= Ee) return;
    int s = ei[i], d = ei[Ee + i];
    int pos = g_row[d] + atomicAdd(&g_cur[d], 1);
    g_csr[pos] = s;
}

// ---------------- K6: gather-aggregate per dst node (no atomics) -------------
// One warp per dst node. Lane l owns features [4l,4l+3], head = l>>3.
// Accumulates sum(ex*h[src]) and den=sum(ex) in registers; normalizes,
// adds bias, applies relu, writes row once.
__global__ void agg_kernel(const float* __restrict__ bias) {
    int w = (blockIdx.x * blockDim.x + threadIdx.x) >> 5;
    int lane = threadIdx.x & 31;
    if (w >= Nn) return;
    int hd = lane >> 3;
    const float ad = g_adst[w * 4 + hd];

    float4 acc = make_float4(0.f, 0.f, 0.f, 0.f);
    float den = 0.f;

    // self loop
    {
        float e = g_asrc[w * 4 + hd] + ad;
        e = e > 0.f ? e : NEG * e;
        float ex = __expf(e);
        float4 hv = ((const float4*)g_h)[(size_t)w * 32 + lane];
        acc.x += ex * hv.x; acc.y += ex * hv.y;
        acc.z += ex * hv.z; acc.w += ex * hv.w;
        den += ex;
    }

    int start = g_row[w];
    int len = g_cnt[w];
    int j = 0;
    for (; j + 4 <= len; j += 4) {
        int s0 = g_csr[start + j];
        int s1 = g_csr[start + j + 1];
        int s2 = g_csr[start + j + 2];
        int s3 = g_csr[start + j + 3];
        float4 h0 = ((const float4*)g_h)[(size_t)s0 * 32 + lane];
        float4 h1 = ((const float4*)g_h)[(size_t)s1 * 32 + lane];
        float4 h2 = ((const float4*)g_h)[(size_t)s2 * 32 + lane];
        float4 h3 = ((const float4*)g_h)[(size_t)s3 * 32 + lane];
        float e0 = g_asrc[s0 * 4 + hd] + ad;
        float e1 = g_asrc[s1 * 4 + hd] + ad;
        float e2 = g_asrc[s2 * 4 + hd] + ad;
        float e3 = g_asrc[s3 * 4 + hd] + ad;
        e0 = e0 > 0.f ? e0 : NEG * e0;  float x0 = __expf(e0);
        e1 = e1 > 0.f ? e1 : NEG * e1;  float x1 = __expf(e1);
        e2 = e2 > 0.f ? e2 : NEG * e2;  float x2 = __expf(e2);
        e3 = e3 > 0.f ? e3 : NEG * e3;  float x3 = __expf(e3);
        acc.x += x0 * h0.x; acc.y += x0 * h0.y; acc.z += x0 * h0.z; acc.w += x0 * h0.w;
        acc.x += x1 * h1.x; acc.y += x1 * h1.y; acc.z += x1 * h1.z; acc.w += x1 * h1.w;
        acc.x += x2 * h2.x; acc.y += x2 * h2.y; acc.z += x2 * h2.z; acc.w += x2 * h2.w;
        acc.x += x3 * h3.x; acc.y += x3 * h3.y; acc.z += x3 * h3.z; acc.w += x3 * h3.w;
        den += x0 + x1 + x2 + x3;
    }
    for (; j < len; j++) {
        int s = g_csr[start + j];
        float e = g_asrc[s * 4 + hd] + ad;
        e = e > 0.f ? e : NEG * e;
        float ex = __expf(e);
        float4 hv = ((const float4*)g_h)[(size_t)s * 32 + lane];
        acc.x += ex * hv.x; acc.y += ex * hv.y;
        acc.z += ex * hv.z; acc.w += ex * hv.w;
        den += ex;
    }

    float rden = 1.f / (den + 1e-16f);
    float4 b = ((const float4*)bias)[lane];
    float4 o;
    o.x = fmaxf(acc.x * rden + b.x, 0.f);
    o.y = fmaxf(acc.y * rden + b.y, 0.f);
    o.z = fmaxf(acc.z * rden + b.z, 0.f);
    o.w = fmaxf(acc.w * rden + b.w, 0.f);
    ((float4*)g_agg)[(size_t)w * 32 + lane] = o;
}

// ---------------- K7: BN partial sums (read-only) ----------------------------
__global__ void bn_reduce_kernel() {
    int f = threadIdx.x;
    float s = 0.f, q = 0.f;
    for (int n = blockIdx.x; n < Nn; n += gridDim.x) {
        float v = g_agg[(size_t)n * 128 + f];
        s += v;
        q += v * v;
    }
    atomicAdd(&g_bns[f], s);
    atomicAdd(&g_bnq[f], q);
}

// ---------------- K8: BN normalize + write output ----------------------------
__global__ void bn_apply_kernel(const float* __restrict__ gamma,
                                const float* __restrict__ beta,
                                float* __restrict__ out) {
    int i = blockIdx.x * blockDim.x + threadIdx.x;
    if (i >= Nn * 128) return;
    int f = i & 127;
    const float invn = 1.f / (float)Nn;
    float mean = g_bns[f] * invn;
    float var = g_bnq[f] * invn - mean * mean;
    out[i] = (g_agg[i] - mean) * rsqrtf(var + BN_EPS) * gamma[f] + beta[f];
}

// ---------------- launch ------------------------------------------------------
extern "C" void kernel_launch(void* const* d_in, const int* in_sizes, int n_in,
                              void* d_out, int out_size) {
    (void)in_sizes; (void)n_in; (void)out_size;
    const float* x       = (const float*)d_in[0];
    const int*   ei      = (const int*)d_in[1];
    const float* W       = (const float*)d_in[2];
    const float* att_src = (const float*)d_in[3];
    const float* att_dst = (const float*)d_in[4];
    const float* bias    = (const float*)d_in[5];
    const float* gamma   = (const float*)d_in[6];
    const float* beta    = (const float*)d_in[7];

    void* p;
    cudaGetSymbolAddress(&p, g_cnt);  cudaMemsetAsync(p, 0, sizeof(int) * Nn);
    cudaGetSymbolAddress(&p, g_cur);  cudaMemsetAsync(p, 0, sizeof(int) * Nn);
    cudaGetSymbolAddress(&p, g_bns);  cudaMemsetAsync(p, 0, sizeof(float) * Ff);
    cudaGetSymbolAddress(&p, g_bnq);  cudaMemsetAsync(p, 0, sizeof(float) * Ff);

    gemm_kernel<<<(Nn + 63) / 64, 256>>>(x, W);
    att_kernel<<<(Nn * 32 + 255) / 256, 256>>>(att_src, att_dst);

    hist_kernel<<<(Ee + 255) / 256, 256>>>(ei);
    scan1_kernel<<<NB, 256>>>();
    scan2_kernel<<<1, 256>>>();
    scan3_kernel<<<NB, 256>>>();
    scatter_kernel<<<(Ee + 255) / 256, 256>>>(ei);

    agg_kernel<<<(Nn + 7) / 8, 256>>>(bias);        // 1 warp / node

    bn_reduce_kernel<<<592, 128>>>();
    bn_apply_kernel<<<(Nn * 128 + 255) / 256, 256>>>(gamma, beta, (float*)d_out);
}

// round 4
// speedup vs baseline: 1.6615x; 1.2375x over previous
#include <cuda_runtime.h>
#include <math.h>

#define Nn 50000
#define Ee 800000
#define Hh 4
#define Ff 128
#define NEG 0.2f
#define BN_EPS 1e-5f
#define NB 196            // ceil(50000/256) scan blocks

// ---------------- scratch (device globals) ----------------------------------
__device__ __align__(16) float g_h[(size_t)Nn * Ff];     // projected features [N,128]
__device__ __align__(16) float g_asrc[Nn * Hh];          // per-node src attention logits
__device__ __align__(16) float g_adst[Nn * Hh];          // per-node dst attention logits
__device__ __align__(16) float g_agg[(size_t)Nn * Ff];   // aggregated (pre-BN) output
__device__ int   g_cnt[Nn];                               // in-degree (no self loop)
__device__ int   g_cur[Nn];                               // scatter cursor
__device__ int   g_row[Nn];                               // CSR row starts
__device__ int   g_bsum[NB];                              // scan block sums
__device__ int   g_boff[NB];                              // scanned block offsets
__device__ int   g_csr[Ee];                               // src node per CSR slot
__device__ float g_bns[Ff];                               // BN sum per feature
__device__ float g_bnq[Ff];                               // BN sumsq per feature

// ---------------- K1: h = x @ W^T + fused attention logits -------------------
// Block: 64 rows x 128 cols, 256 threads, 4x8 register tile per thread.
// Epilogue computes a_src/a_dst for the block's 64 rows from the register tile.
__global__ void gemm_att_kernel(const float* __restrict__ x,
                                const float* __restrict__ W,
                                const float* __restrict__ att_src,
                                const float* __restrict__ att_dst) {
    __shared__ float xs[64 * 33];
    __shared__ float wt[32 * 132];
    __shared__ float s_as[64 * 4];   // [row][head] src partials
    __shared__ float s_ad[64 * 4];
    int tid = threadIdx.x;
    int row0 = blockIdx.x * 64;
    int cg = tid & 15;   // cols cg*8 .. cg*8+7
    int rg = tid >> 4;   // rows rg*4 .. rg*4+3

    s_as[tid] = 0.f;
    s_ad[tid] = 0.f;

    float acc[4][8];
#pragma unroll
    for (int i = 0; i < 4; i++)
#pragma unroll
        for (int j = 0; j < 8; j++) acc[i][j] = 0.f;

    for (int kb = 0; kb < 128; kb += 32) {
#pragma unroll
        for (int i = 0; i < 8; i++) {
            int lin = i * 256 + tid;
            int r = lin >> 5, k = lin & 31;
            int gr = row0 + r;
            xs[r * 33 + k] = (gr < Nn) ? x[(size_t)gr * 128 + kb + k] : 0.f;
        }
#pragma unroll
        for (int i = 0; i < 16; i++) {
            int lin = i * 256 + tid;
            int f = lin >> 5, k = lin & 31;
            wt[k * 132 + f] = W[f * 128 + kb + k];
        }
        __syncthreads();
#pragma unroll
        for (int k = 0; k < 32; k++) {
            float xv[4];
#pragma unroll
            for (int i = 0; i < 4; i++) xv[i] = xs[(rg * 4 + i) * 33 + k];
            float4 w0 = *(float4*)&wt[k * 132 + cg * 8];
            float4 w1 = *(float4*)&wt[k * 132 + cg * 8 + 4];
#pragma unroll
            for (int i = 0; i < 4; i++) {
                acc[i][0] += xv[i] * w0.x; acc[i][1] += xv[i] * w0.y;
                acc[i][2] += xv[i] * w0.z; acc[i][3] += xv[i] * w0.w;
                acc[i][4] += xv[i] * w1.x; acc[i][5] += xv[i] * w1.y;
                acc[i][6] += xv[i] * w1.z; acc[i][7] += xv[i] * w1.w;
            }
        }
        __syncthreads();
    }

    // att vectors for this thread's 8 columns (global col = head*32+channel)
    float4 as0 = ((const float4*)att_src)[cg * 2];
    float4 as1 = ((const float4*)att_src)[cg * 2 + 1];
    float4 ad0 = ((const float4*)att_dst)[cg * 2];
    float4 ad1 = ((const float4*)att_dst)[cg * 2 + 1];
    int head = cg >> 2;   // cols cg*8..cg*8+7 all inside head cg>>2

#pragma unroll
    for (int i = 0; i < 4; i++) {
        int gr = row0 + rg * 4 + i;
        if (gr < Nn) {
            *(float4*)&g_h[(size_t)gr * 128 + cg * 8] =
                make_float4(acc[i][0], acc[i][1], acc[i][2], acc[i][3]);
            *(float4*)&g_h[(size_t)gr * 128 + cg * 8 + 4] =
                make_float4(acc[i][4], acc[i][5], acc[i][6], acc[i][7]);
        }
        float ps = acc[i][0]*as0.x + acc[i][1]*as0.y + acc[i][2]*as0.z + acc[i][3]*as0.w
                 + acc[i][4]*as1.x + acc[i][5]*as1.y + acc[i][6]*as1.z + acc[i][7]*as1.w;
        float pd = acc[i][0]*ad0.x + acc[i][1]*ad0.y + acc[i][2]*ad0.z + acc[i][3]*ad0.w
                 + acc[i][4]*ad1.x + acc[i][5]*ad1.y + acc[i][6]*ad1.z + acc[i][7]*ad1.w;
        atomicAdd(&s_as[(rg * 4 + i) * 4 + head], ps);
        atomicAdd(&s_ad[(rg * 4 + i) * 4 + head], pd);
    }
    __syncthreads();
    // flush 64 rows x 4 heads (256 values each array)
    {
        int r = tid >> 2, hd = tid & 3;
        int gr = row0 + r;
        if (gr < Nn) {
            g_asrc[gr * 4 + hd] = s_as[tid];
            g_adst[gr * 4 + hd] = s_ad[tid];
        }
    }
}

// ---------------- CSR build: histogram / scan / scatter ----------------------
__global__ void hist_kernel(const int* __restrict__ ei) {
    int i = blockIdx.x * blockDim.x + threadIdx.x;
    if (i >= Ee) return;
    atomicAdd(&g_cnt[ei[Ee + i]], 1);
}

__global__ void scan1_kernel() {
    int i = blockIdx.x * 256 + threadIdx.x;
    int lane = threadIdx.x & 31, wid = threadIdx.x >> 5;
    int v = (i < Nn) ? g_cnt[i] : 0;
    int x = v;
#pragma unroll
    for (int o = 1; o < 32; o <<= 1) {
        int y = __shfl_up_sync(0xFFFFFFFFu, x, o);
        if (lane >= o) x += y;
    }
    __shared__ int wsum[8];
    if (lane == 31) wsum[wid] = x;
    __syncthreads();
    if (wid == 0 && lane < 8) {
        int t = wsum[lane];
        int xx = t;
#pragma unroll
        for (int o = 1; o < 8; o <<= 1) {
            int y = __shfl_up_sync(0xFFu, xx, o);
            if (lane >= o) xx += y;
        }
        wsum[lane] = xx - t;
    }
    __syncthreads();
    int incl = x + wsum[wid];
    if (i < Nn) g_row[i] = incl - v;
    if (threadIdx.x == 255) g_bsum[blockIdx.x] = incl;
}

__global__ void scan2_kernel() {
    int lane = threadIdx.x & 31, wid = threadIdx.x >> 5;
    int v = (threadIdx.x < NB) ? g_bsum[threadIdx.x] : 0;
    int x = v;
#pragma unroll
    for (int o = 1; o < 32; o <<= 1) {
        int y = __shfl_up_sync(0xFFFFFFFFu, x, o);
        if (lane >= o) x += y;
    }
    __shared__ int wsum[8];
    if (lane == 31) wsum[wid] = x;
    __syncthreads();
    if (wid == 0 && lane < 8) {
        int t = wsum[lane];
        int xx = t;
#pragma unroll
        for (int o = 1; o < 8; o <<= 1) {
            int y = __shfl_up_sync(0xFFu, xx, o);
            if (lane >= o) xx += y;
        }
        wsum[lane] = xx - t;
    }
    __syncthreads();
    if (threadIdx.x < NB) g_boff[threadIdx.x] = x + wsum[wid] - v;
}

__global__ void scan3_kernel() {
    int i = blockIdx.x * 256 + threadIdx.x;
    if (i < Nn) g_row[i] += g_boff[blockIdx.x];
}

__global__ void scatter_kernel(const int* __restrict__ ei) {
    int i = blockIdx.x * blockDim.x + threadIdx.x;
    if (i >= Ee) return;
    int s = ei[i], d = ei[Ee + i];
    int pos = g_row[d] + atomicAdd(&g_cur[d], 1);
    g_csr[pos] = s;
}

// ---------------- K6: gather-aggregate + fused BN partial sums ---------------
// Warp-stride over dst nodes. Lane l owns features [4l,4l+3], head = l>>3.
__global__ void agg_kernel(const float* __restrict__ bias) {
    int lane = threadIdx.x & 31;
    int warp = (blockIdx.x * blockDim.x + threadIdx.x) >> 5;
    int nwarps = (gridDim.x * blockDim.x) >> 5;
    int hd = lane >> 3;

    __shared__ float sh_s[128];
    __shared__ float sh_q[128];
    if (threadIdx.x < 128) { sh_s[threadIdx.x] = 0.f; sh_q[threadIdx.x] = 0.f; }
    __syncthreads();

    float4 b = ((const float4*)bias)[lane];
    float bs_x = 0.f, bs_y = 0.f, bs_z = 0.f, bs_w = 0.f;   // BN sums
    float bq_x = 0.f, bq_y = 0.f, bq_z = 0.f, bq_w = 0.f;   // BN sumsqs

    for (int w = warp; w < Nn; w += nwarps) {
        const float ad = g_adst[w * 4 + hd];
        float4 acc = make_float4(0.f, 0.f, 0.f, 0.f);
        float den = 0.f;

        // self loop
        {
            float e = g_asrc[w * 4 + hd] + ad;
            e = e > 0.f ? e : NEG * e;
            float ex = __expf(e);
            float4 hv = ((const float4*)g_h)[(size_t)w * 32 + lane];
            acc.x += ex * hv.x; acc.y += ex * hv.y;
            acc.z += ex * hv.z; acc.w += ex * hv.w;
            den += ex;
        }

        int start = g_row[w];
        int len = g_cnt[w];
        int j = 0;
        for (; j + 8 <= len; j += 8) {
            int si[8];
#pragma unroll
            for (int u = 0; u < 8; u++) si[u] = g_csr[start + j + u];
            float4 hv[8];
#pragma unroll
            for (int u = 0; u < 8; u++)
                hv[u] = ((const float4*)g_h)[(size_t)si[u] * 32 + lane];
            float ev[8];
#pragma unroll
            for (int u = 0; u < 8; u++) {
                float e = g_asrc[si[u] * 4 + hd] + ad;
                e = e > 0.f ? e : NEG * e;
                ev[u] = __expf(e);
            }
#pragma unroll
            for (int u = 0; u < 8; u++) {
                acc.x += ev[u] * hv[u].x; acc.y += ev[u] * hv[u].y;
                acc.z += ev[u] * hv[u].z; acc.w += ev[u] * hv[u].w;
                den += ev[u];
            }
        }
        for (; j < len; j++) {
            int s = g_csr[start + j];
            float e = g_asrc[s * 4 + hd] + ad;
            e = e > 0.f ? e : NEG * e;
            float ex = __expf(e);
            float4 hv = ((const float4*)g_h)[(size_t)s * 32 + lane];
            acc.x += ex * hv.x; acc.y += ex * hv.y;
            acc.z += ex * hv.z; acc.w += ex * hv.w;
            den += ex;
        }

        float rden = 1.f / (den + 1e-16f);
        float4 o;
        o.x = fmaxf(acc.x * rden + b.x, 0.f);
        o.y = fmaxf(acc.y * rden + b.y, 0.f);
        o.z = fmaxf(acc.z * rden + b.z, 0.f);
        o.w = fmaxf(acc.w * rden + b.w, 0.f);
        ((float4*)g_agg)[(size_t)w * 32 + lane] = o;

        bs_x += o.x; bs_y += o.y; bs_z += o.z; bs_w += o.w;
        bq_x += o.x * o.x; bq_y += o.y * o.y; bq_z += o.z * o.z; bq_w += o.w * o.w;
    }

    // block-level BN reduction: feature f = lane*4+c, 8 warps contend per addr
    atomicAdd(&sh_s[lane * 4 + 0], bs_x);
    atomicAdd(&sh_s[lane * 4 + 1], bs_y);
    atomicAdd(&sh_s[lane * 4 + 2], bs_z);
    atomicAdd(&sh_s[lane * 4 + 3], bs_w);
    atomicAdd(&sh_q[lane * 4 + 0], bq_x);
    atomicAdd(&sh_q[lane * 4 + 1], bq_y);
    atomicAdd(&sh_q[lane * 4 + 2], bq_z);
    atomicAdd(&sh_q[lane * 4 + 3], bq_w);
    __syncthreads();
    if (threadIdx.x < 128) atomicAdd(&g_bns[threadIdx.x], sh_s[threadIdx.x]);
    else if (threadIdx.x < 256) atomicAdd(&g_bnq[threadIdx.x - 128], sh_q[threadIdx.x - 128]);
}

// ---------------- K8: BN normalize + write output ----------------------------
__global__ void bn_apply_kernel(const float* __restrict__ gamma,
                                const float* __restrict__ beta,
                                float* __restrict__ out) {
    int i = (blockIdx.x * blockDim.x + threadIdx.x) * 4;
    if (i >= Nn * 128) return;
    int f = i & 127;
    const float invn = 1.f / (float)Nn;
    float4 v = *(const float4*)&g_agg[i];
    float4 s = *(const float4*)&g_bns[f];
    float4 q = *(const float4*)&g_bnq[f];
    float4 gm = *(const float4*)&gamma[f];
    float4 bt = *(const float4*)&beta[f];
    float m0 = s.x * invn, m1 = s.y * invn, m2 = s.z * invn, m3 = s.w * invn;
    float4 o;
    o.x = (v.x - m0) * rsqrtf(q.x * invn - m0 * m0 + BN_EPS) * gm.x + bt.x;
    o.y = (v.y - m1) * rsqrtf(q.y * invn - m1 * m1 + BN_EPS) * gm.y + bt.y;
    o.z = (v.z - m2) * rsqrtf(q.z * invn - m2 * m2 + BN_EPS) * gm.z + bt.z;
    o.w = (v.w - m3) * rsqrtf(q.w * invn - m3 * m3 + BN_EPS) * gm.w + bt.w;
    *(float4*)&out[i] = o;
}

// ---------------- launch ------------------------------------------------------
extern "C" void kernel_launch(void* const* d_in, const int* in_sizes, int n_in,
                              void* d_out, int out_size) {
    (void)in_sizes; (void)n_in; (void)out_size;
    const float* x       = (const float*)d_in[0];
    const int*   ei      = (const int*)d_in[1];
    const float* W       = (const float*)d_in[2];
    const float* att_src = (const float*)d_in[3];
    const float* att_dst = (const float*)d_in[4];
    const float* bias    = (const float*)d_in[5];
    const float* gamma   = (const float*)d_in[6];
    const float* beta    = (const float*)d_in[7];

    // side stream for the independent CSR build (fork-join inside capture)
    cudaStream_t s2;
    cudaStreamCreateWithFlags(&s2, cudaStreamNonBlocking);
    cudaEvent_t eFork, eJoin;
    cudaEventCreateWithFlags(&eFork, cudaEventDisableTiming);
    cudaEventCreateWithFlags(&eJoin, cudaEventDisableTiming);

    cudaEventRecord(eFork, 0);
    cudaStreamWaitEvent(s2, eFork, 0);

    void* p;
    // CSR branch (stream s2)
    cudaGetSymbolAddress(&p, g_cnt);  cudaMemsetAsync(p, 0, sizeof(int) * Nn, s2);
    cudaGetSymbolAddress(&p, g_cur);  cudaMemsetAsync(p, 0, sizeof(int) * Nn, s2);
    hist_kernel<<<(Ee + 255) / 256, 256, 0, s2>>>(ei);
    scan1_kernel<<<NB, 256, 0, s2>>>();
    scan2_kernel<<<1, 256, 0, s2>>>();
    scan3_kernel<<<NB, 256, 0, s2>>>();
    scatter_kernel<<<(Ee + 255) / 256, 256, 0, s2>>>(ei);

    // main branch (stream 0)
    cudaGetSymbolAddress(&p, g_bns);  cudaMemsetAsync(p, 0, sizeof(float) * Ff);
    cudaGetSymbolAddress(&p, g_bnq);  cudaMemsetAsync(p, 0, sizeof(float) * Ff);
    gemm_att_kernel<<<(Nn + 63) / 64, 256>>>(x, W, att_src, att_dst);

    cudaEventRecord(eJoin, s2);
    cudaStreamWaitEvent(0, eJoin, 0);

    agg_kernel<<<592, 256>>>(bias);   // warp-stride: 4736 warps over 50k nodes
    bn_apply_kernel<<<(Nn * 128 / 4 + 255) / 256, 256>>>(gamma, beta, (float*)d_out);

    cudaStreamDestroy(s2);
    cudaEventDestroy(eFork);
    cudaEventDestroy(eJoin);
}

// round 5
// speedup vs baseline: 2.2831x; 1.3742x over previous
#include <cuda_runtime.h>
#include <math.h>
#include <stdint.h>

#define Nn 50000
#define Ee 800000
#define Hh 4
#define Ff 128
#define NEG 0.2f
#define BN_EPS 1e-5f
#define NB 196            // ceil(50000/256) scan blocks

// ---------------- scratch (device globals) ----------------------------------
__device__ __align__(16) float g_h[(size_t)Nn * Ff];     // projected features [N,128]
__device__ __align__(16) float g_asrc[Nn * Hh];          // per-node src attention logits
__device__ __align__(16) float g_adst[Nn * Hh];          // per-node dst attention logits
__device__ __align__(16) float g_agg[(size_t)Nn * Ff];   // aggregated (pre-BN) output
__device__ int   g_cnt[Nn];                               // in-degree (no self loop)
__device__ int   g_cur[Nn];                               // scatter cursor
__device__ int   g_row[Nn];                               // CSR row starts
__device__ int   g_bsum[NB];                              // scan block sums
__device__ int   g_boff[NB];                              // scanned block offsets
__device__ int   g_csr[Ee];                               // src node per CSR slot
__device__ float g_bns[Ff];                               // BN sum per feature
__device__ float g_bnq[Ff];                               // BN sumsq per feature

__device__ __forceinline__ uint32_t f2tf(float f) {
    uint32_t u;
    asm("cvt.rna.tf32.f32 %0, %1;" : "=r"(u) : "f"(f));
    return u;
}

__device__ __forceinline__ void mma_tf32(float c[4], uint32_t a0, uint32_t a1,
                                         uint32_t a2, uint32_t a3,
                                         uint32_t b0, uint32_t b1) {
    asm volatile(
        "mma.sync.aligned.m16n8k8.row.col.f32.tf32.tf32.f32 "
        "{%0,%1,%2,%3}, {%4,%5,%6,%7}, {%8,%9}, {%0,%1,%2,%3};"
        : "+f"(c[0]), "+f"(c[1]), "+f"(c[2]), "+f"(c[3])
        : "r"(a0), "r"(a1), "r"(a2), "r"(a3), "r"(b0), "r"(b1));
}

// ---------------- K1: h = x @ W^T (tf32 tensor cores) + fused att logits -----
// Block: 256 threads (8 warps), tile 128 rows x 128 cols.
// Warp w computes rows [w*16, w*16+16) x all 128 cols via m16n8k8 mma.
__global__ void gemm_att_kernel(const float* __restrict__ x,
                                const float* __restrict__ W,
                                const float* __restrict__ att_src,
                                const float* __restrict__ att_dst) {
    __shared__ uint32_t xs[128][36];    // x tile, tf32 bits, pad 36
    __shared__ uint32_t ws[32][136];    // W^T chunk [k][f], tf32 bits, pad 136
    int tid = threadIdx.x;
    int warp = tid >> 5, lane = tid & 31;
    int qid = lane >> 2;    // 0..7
    int tq  = lane & 3;     // 0..3
    int row0 = blockIdx.x * 128;

    float c[16][4];
#pragma unroll
    for (int i = 0; i < 16; i++)
#pragma unroll
        for (int j = 0; j < 4; j++) c[i][j] = 0.f;

    for (int kb = 0; kb < 128; kb += 32) {
        // stage x tile: 128 rows x 32 k (coalesced: 8 lanes per row)
#pragma unroll
        for (int i = 0; i < 4; i++) {
            int lin = i * 256 + tid;     // float4 slot
            int r = lin >> 3;
            int c4 = (lin & 7) * 4;
            int gr = row0 + r;
            float4 v = (gr < Nn) ? *(const float4*)&x[(size_t)gr * 128 + kb + c4]
                                 : make_float4(0.f, 0.f, 0.f, 0.f);
            uint32_t* dst = &xs[r][c4];
            dst[0] = f2tf(v.x); dst[1] = f2tf(v.y);
            dst[2] = f2tf(v.z); dst[3] = f2tf(v.w);
        }
        // stage W chunk transposed: lane owns one f row -> bank-conflict-free stores
#pragma unroll
        for (int i = 0; i < 4; i++) {
            int lin = i * 256 + tid;
            int f  = lin & 127;
            int c4 = (lin >> 7) * 4;     // 0,4,...,28
            float4 v = *(const float4*)&W[f * 128 + kb + c4];
            ws[c4 + 0][f] = f2tf(v.x);
            ws[c4 + 1][f] = f2tf(v.y);
            ws[c4 + 2][f] = f2tf(v.z);
            ws[c4 + 3][f] = f2tf(v.w);
        }
        __syncthreads();
#pragma unroll
        for (int ks = 0; ks < 4; ks++) {
            int k0 = ks * 8;
            int r = warp * 16 + qid;
            uint32_t a0 = xs[r][k0 + tq];
            uint32_t a1 = xs[r + 8][k0 + tq];
            uint32_t a2 = xs[r][k0 + tq + 4];
            uint32_t a3 = xs[r + 8][k0 + tq + 4];
#pragma unroll
            for (int nt = 0; nt < 16; nt++) {
                uint32_t b0 = ws[k0 + tq][nt * 8 + qid];
                uint32_t b1 = ws[k0 + tq + 4][nt * 8 + qid];
                mma_tf32(c[nt], a0, a1, a2, a3, b0, b1);
            }
        }
        __syncthreads();
    }

    // epilogue: write h rows + per-row attention dots
    int r0 = row0 + warp * 16 + qid;
    int r1 = r0 + 8;
    float ps0[4] = {0,0,0,0}, ps1[4] = {0,0,0,0};
    float pd0[4] = {0,0,0,0}, pd1[4] = {0,0,0,0};
#pragma unroll
    for (int nt = 0; nt < 16; nt++) {
        int col = nt * 8 + 2 * tq;
        int head = nt >> 2;
        if (r0 < Nn)
            *(float2*)&g_h[(size_t)r0 * 128 + col] = make_float2(c[nt][0], c[nt][1]);
        if (r1 < Nn)
            *(float2*)&g_h[(size_t)r1 * 128 + col] = make_float2(c[nt][2], c[nt][3]);
        float as0 = att_src[col], as1 = att_src[col + 1];
        float ad0 = att_dst[col], ad1 = att_dst[col + 1];
        ps0[head] += c[nt][0] * as0 + c[nt][1] * as1;
        ps1[head] += c[nt][2] * as0 + c[nt][3] * as1;
        pd0[head] += c[nt][0] * ad0 + c[nt][1] * ad1;
        pd1[head] += c[nt][2] * ad0 + c[nt][3] * ad1;
    }
    // reduce across the 4 lanes of each quad (same row)
#pragma unroll
    for (int hd = 0; hd < 4; hd++) {
        ps0[hd] += __shfl_down_sync(0xFFFFFFFFu, ps0[hd], 1);
        ps0[hd] += __shfl_down_sync(0xFFFFFFFFu, ps0[hd], 2);
        ps1[hd] += __shfl_down_sync(0xFFFFFFFFu, ps1[hd], 1);
        ps1[hd] += __shfl_down_sync(0xFFFFFFFFu, ps1[hd], 2);
        pd0[hd] += __shfl_down_sync(0xFFFFFFFFu, pd0[hd], 1);
        pd0[hd] += __shfl_down_sync(0xFFFFFFFFu, pd0[hd], 2);
        pd1[hd] += __shfl_down_sync(0xFFFFFFFFu, pd1[hd], 1);
        pd1[hd] += __shfl_down_sync(0xFFFFFFFFu, pd1[hd], 2);
    }
    if (tq == 0) {
        if (r0 < Nn) {
#pragma unroll
            for (int hd = 0; hd < 4; hd++) {
                g_asrc[r0 * 4 + hd] = ps0[hd];
                g_adst[r0 * 4 + hd] = pd0[hd];
            }
        }
        if (r1 < Nn) {
#pragma unroll
            for (int hd = 0; hd < 4; hd++) {
                g_asrc[r1 * 4 + hd] = ps1[hd];
                g_adst[r1 * 4 + hd] = pd1[hd];
            }
        }
    }
}

// ---------------- CSR build: histogram / scan / scatter ----------------------
__global__ void hist_kernel(const int* __restrict__ ei) {
    int i = blockIdx.x * blockDim.x + threadIdx.x;
    if (i >= Ee) return;
    atomicAdd(&g_cnt[ei[Ee + i]], 1);
}

__global__ void scan1_kernel() {
    int i = blockIdx.x * 256 + threadIdx.x;
    int lane = threadIdx.x & 31, wid = threadIdx.x >> 5;
    int v = (i < Nn) ? g_cnt[i] : 0;
    int x = v;
#pragma unroll
    for (int o = 1; o < 32; o <<= 1) {
        int y = __shfl_up_sync(0xFFFFFFFFu, x, o);
        if (lane >= o) x += y;
    }
    __shared__ int wsum[8];
    if (lane == 31) wsum[wid] = x;
    __syncthreads();
    if (wid == 0 && lane < 8) {
        int t = wsum[lane];
        int xx = t;
#pragma unroll
        for (int o = 1; o < 8; o <<= 1) {
            int y = __shfl_up_sync(0xFFu, xx, o);
            if (lane >= o) xx += y;
        }
        wsum[lane] = xx - t;
    }
    __syncthreads();
    int incl = x + wsum[wid];
    if (i < Nn) g_row[i] = incl - v;
    if (threadIdx.x == 255) g_bsum[blockIdx.x] = incl;
}

__global__ void scan2_kernel() {
    int lane = threadIdx.x & 31, wid = threadIdx.x >> 5;
    int v = (threadIdx.x < NB) ? g_bsum[threadIdx.x] : 0;
    int x = v;
#pragma unroll
    for (int o = 1; o < 32; o <<= 1) {
        int y = __shfl_up_sync(0xFFFFFFFFu, x, o);
        if (lane >= o) x += y;
    }
    __shared__ int wsum[8];
    if (lane == 31) wsum[wid] = x;
    __syncthreads();
    if (wid == 0 && lane < 8) {
        int t = wsum[lane];
        int xx = t;
#pragma unroll
        for (int o = 1; o < 8; o <<= 1) {
            int y = __shfl_up_sync(0xFFu, xx, o);
            if (lane >= o) xx += y;
        }
        wsum[lane] = xx - t;
    }
    __syncthreads();
    if (threadIdx.x < NB) g_boff[threadIdx.x] = x + wsum[wid] - v;
}

__global__ void scan3_kernel() {
    int i = blockIdx.x * 256 + threadIdx.x;
    if (i < Nn) g_row[i] += g_boff[blockIdx.x];
}

__global__ void scatter_kernel(const int* __restrict__ ei) {
    int i = blockIdx.x * blockDim.x + threadIdx.x;
    if (i >= Ee) return;
    int s = ei[i], d = ei[Ee + i];
    int pos = g_row[d] + atomicAdd(&g_cur[d], 1);
    g_csr[pos] = s;
}

// ---------------- K6: gather-aggregate + fused BN partial sums ---------------
// Warp-stride over dst nodes. Lane l owns features [4l,4l+3], head = l>>3.
// Fully predicated unroll-8 keeps 8 gathers in flight through the tail.
__global__ void agg_kernel(const float* __restrict__ bias) {
    int lane = threadIdx.x & 31;
    int warp = (blockIdx.x * blockDim.x + threadIdx.x) >> 5;
    int nwarps = (gridDim.x * blockDim.x) >> 5;
    int hd = lane >> 3;

    __shared__ float sh_s[128];
    __shared__ float sh_q[128];
    if (threadIdx.x < 128) { sh_s[threadIdx.x] = 0.f; sh_q[threadIdx.x] = 0.f; }
    __syncthreads();

    float4 b = ((const float4*)bias)[lane];
    float bs_x = 0.f, bs_y = 0.f, bs_z = 0.f, bs_w = 0.f;
    float bq_x = 0.f, bq_y = 0.f, bq_z = 0.f, bq_w = 0.f;

    for (int w = warp; w < Nn; w += nwarps) {
        const float ad = g_adst[w * 4 + hd];
        float4 acc = make_float4(0.f, 0.f, 0.f, 0.f);
        float den = 0.f;

        // self loop
        {
            float e = g_asrc[w * 4 + hd] + ad;
            e = e > 0.f ? e : NEG * e;
            float ex = __expf(e);
            float4 hv = ((const float4*)g_h)[(size_t)w * 32 + lane];
            acc.x += ex * hv.x; acc.y += ex * hv.y;
            acc.z += ex * hv.z; acc.w += ex * hv.w;
            den += ex;
        }

        int start = g_row[w];
        int len = g_cnt[w];
        for (int j = 0; j < len; j += 8) {
            int rem = len - j;   // >= 1
            int si[8];
#pragma unroll
            for (int u = 0; u < 8; u++) {
                int jj = (u < rem) ? j + u : j;   // clamp to a valid slot
                si[u] = __ldg(&g_csr[start + jj]);
            }
            float4 hv[8];
#pragma unroll
            for (int u = 0; u < 8; u++)
                hv[u] = ((const float4*)g_h)[(size_t)si[u] * 32 + lane];
            float ev[8];
#pragma unroll
            for (int u = 0; u < 8; u++) {
                float e = g_asrc[si[u] * 4 + hd] + ad;
                e = e > 0.f ? e : NEG * e;
                float ex = __expf(e);
                ev[u] = (u < rem) ? ex : 0.f;
            }
#pragma unroll
            for (int u = 0; u < 8; u++) {
                acc.x += ev[u] * hv[u].x; acc.y += ev[u] * hv[u].y;
                acc.z += ev[u] * hv[u].z; acc.w += ev[u] * hv[u].w;
                den += ev[u];
            }
        }

        float rden = 1.f / (den + 1e-16f);
        float4 o;
        o.x = fmaxf(acc.x * rden + b.x, 0.f);
        o.y = fmaxf(acc.y * rden + b.y, 0.f);
        o.z = fmaxf(acc.z * rden + b.z, 0.f);
        o.w = fmaxf(acc.w * rden + b.w, 0.f);
        ((float4*)g_agg)[(size_t)w * 32 + lane] = o;

        bs_x += o.x; bs_y += o.y; bs_z += o.z; bs_w += o.w;
        bq_x += o.x * o.x; bq_y += o.y * o.y; bq_z += o.z * o.z; bq_w += o.w * o.w;
    }

    atomicAdd(&sh_s[lane * 4 + 0], bs_x);
    atomicAdd(&sh_s[lane * 4 + 1], bs_y);
    atomicAdd(&sh_s[lane * 4 + 2], bs_z);
    atomicAdd(&sh_s[lane * 4 + 3], bs_w);
    atomicAdd(&sh_q[lane * 4 + 0], bq_x);
    atomicAdd(&sh_q[lane * 4 + 1], bq_y);
    atomicAdd(&sh_q[lane * 4 + 2], bq_z);
    atomicAdd(&sh_q[lane * 4 + 3], bq_w);
    __syncthreads();
    if (threadIdx.x < 128) atomicAdd(&g_bns[threadIdx.x], sh_s[threadIdx.x]);
    else if (threadIdx.x < 256) atomicAdd(&g_bnq[threadIdx.x - 128], sh_q[threadIdx.x - 128]);
}

// ---------------- K8: BN normalize + write output ----------------------------
__global__ void bn_apply_kernel(const float* __restrict__ gamma,
                                const float* __restrict__ beta,
                                float* __restrict__ out) {
    int i = (blockIdx.x * blockDim.x + threadIdx.x) * 4;
    if (i >= Nn * 128) return;
    int f = i & 127;
    const float invn = 1.f / (float)Nn;
    float4 v = *(const float4*)&g_agg[i];
    float4 s = *(const float4*)&g_bns[f];
    float4 q = *(const float4*)&g_bnq[f];
    float4 gm = *(const float4*)&gamma[f];
    float4 bt = *(const float4*)&beta[f];
    float m0 = s.x * invn, m1 = s.y * invn, m2 = s.z * invn, m3 = s.w * invn;
    float4 o;
    o.x = (v.x - m0) * rsqrtf(q.x * invn - m0 * m0 + BN_EPS) * gm.x + bt.x;
    o.y = (v.y - m1) * rsqrtf(q.y * invn - m1 * m1 + BN_EPS) * gm.y + bt.y;
    o.z = (v.z - m2) * rsqrtf(q.z * invn - m2 * m2 + BN_EPS) * gm.z + bt.z;
    o.w = (v.w - m3) * rsqrtf(q.w * invn - m3 * m3 + BN_EPS) * gm.w + bt.w;
    *(float4*)&out[i] = o;
}

// ---------------- launch ------------------------------------------------------
extern "C" void kernel_launch(void* const* d_in, const int* in_sizes, int n_in,
                              void* d_out, int out_size) {
    (void)in_sizes; (void)n_in; (void)out_size;
    const float* x       = (const float*)d_in[0];
    const int*   ei      = (const int*)d_in[1];
    const float* W       = (const float*)d_in[2];
    const float* att_src = (const float*)d_in[3];
    const float* att_dst = (const float*)d_in[4];
    const float* bias    = (const float*)d_in[5];
    const float* gamma   = (const float*)d_in[6];
    const float* beta    = (const float*)d_in[7];

    cudaStream_t s2;
    cudaStreamCreateWithFlags(&s2, cudaStreamNonBlocking);
    cudaEvent_t eFork, eJoin;
    cudaEventCreateWithFlags(&eFork, cudaEventDisableTiming);
    cudaEventCreateWithFlags(&eJoin, cudaEventDisableTiming);

    cudaEventRecord(eFork, 0);
    cudaStreamWaitEvent(s2, eFork, 0);

    void* p;
    // CSR branch (stream s2) — overlapped with the GEMM
    cudaGetSymbolAddress(&p, g_cnt);  cudaMemsetAsync(p, 0, sizeof(int) * Nn, s2);
    cudaGetSymbolAddress(&p, g_cur);  cudaMemsetAsync(p, 0, sizeof(int) * Nn, s2);
    hist_kernel<<<(Ee + 255) / 256, 256, 0, s2>>>(ei);
    scan1_kernel<<<NB, 256, 0, s2>>>();
    scan2_kernel<<<1, 256, 0, s2>>>();
    scan3_kernel<<<NB, 256, 0, s2>>>();
    scatter_kernel<<<(Ee + 255) / 256, 256, 0, s2>>>(ei);

    // main branch (stream 0)
    cudaGetSymbolAddress(&p, g_bns);  cudaMemsetAsync(p, 0, sizeof(float) * Ff);
    cudaGetSymbolAddress(&p, g_bnq);  cudaMemsetAsync(p, 0, sizeof(float) * Ff);
    gemm_att_kernel<<<(Nn + 127) / 128, 256>>>(x, W, att_src, att_dst);

    cudaEventRecord(eJoin, s2);
    cudaStreamWaitEvent(0, eJoin, 0);

    agg_kernel<<<592, 256>>>(bias);
    bn_apply_kernel<<<(Nn * 128 / 4 + 255) / 256, 256>>>(gamma, beta, (float*)d_out);

    cudaStreamDestroy(s2);
    cudaEventDestroy(eFork);
    cudaEventDestroy(eJoin);
}

// round 6
// speedup vs baseline: 2.3615x; 1.0343x over previous
#include <cuda_runtime.h>
#include <cuda_fp16.h>
#include <math.h>
#include <stdint.h>

#define Nn 50000
#define Ee 800000
#define Hh 4
#define Ff 128
#define NEG 0.2f
#define BN_EPS 1e-5f
#define NB 196            // ceil(50000/256) scan blocks

// ---------------- scratch (device globals) ----------------------------------
__device__ __align__(16) __half g_h16[(size_t)Nn * Ff];  // projected features, fp16
__device__ __align__(16) float g_asrc[Nn * Hh];          // per-node src attention logits
__device__ __align__(16) float g_adst[Nn * Hh];          // per-node dst attention logits
__device__ __align__(16) float g_agg[(size_t)Nn * Ff];   // aggregated (pre-BN) output
__device__ int   g_cnt[Nn];                               // in-degree (no self loop)
__device__ int   g_cur[Nn];                               // scatter cursor
__device__ int   g_row[Nn];                               // CSR row starts (block-local)
__device__ int   g_bsum[NB];                              // scan block sums
__device__ int   g_boff[NB];                              // scanned block offsets
__device__ int   g_csr[Ee];                               // src node per CSR slot
__device__ float g_bns[Ff];                               // BN sum per feature
__device__ float g_bnq[Ff];                               // BN sumsq per feature

__device__ __forceinline__ uint32_t f2tf(float f) {
    uint32_t u;
    asm("cvt.rna.tf32.f32 %0, %1;" : "=r"(u) : "f"(f));
    return u;
}

__device__ __forceinline__ void mma_tf32(float c[4], uint32_t a0, uint32_t a1,
                                         uint32_t a2, uint32_t a3,
                                         uint32_t b0, uint32_t b1) {
    asm volatile(
        "mma.sync.aligned.m16n8k8.row.col.f32.tf32.tf32.f32 "
        "{%0,%1,%2,%3}, {%4,%5,%6,%7}, {%8,%9}, {%0,%1,%2,%3};"
        : "+f"(c[0]), "+f"(c[1]), "+f"(c[2]), "+f"(c[3])
        : "r"(a0), "r"(a1), "r"(a2), "r"(a3), "r"(b0), "r"(b1));
}

// ---------------- K1: h = x @ W^T (tf32 tensor cores) + fused att logits -----
__global__ void gemm_att_kernel(const float* __restrict__ x,
                                const float* __restrict__ W,
                                const float* __restrict__ att_src,
                                const float* __restrict__ att_dst) {
    __shared__ uint32_t xs[128][36];
    __shared__ uint32_t ws[32][136];
    int tid = threadIdx.x;
    int warp = tid >> 5, lane = tid & 31;
    int qid = lane >> 2;
    int tq  = lane & 3;
    int row0 = blockIdx.x * 128;

    float c[16][4];
#pragma unroll
    for (int i = 0; i < 16; i++)
#pragma unroll
        for (int j = 0; j < 4; j++) c[i][j] = 0.f;

    for (int kb = 0; kb < 128; kb += 32) {
#pragma unroll
        for (int i = 0; i < 4; i++) {
            int lin = i * 256 + tid;
            int r = lin >> 3;
            int c4 = (lin & 7) * 4;
            int gr = row0 + r;
            float4 v = (gr < Nn) ? *(const float4*)&x[(size_t)gr * 128 + kb + c4]
                                 : make_float4(0.f, 0.f, 0.f, 0.f);
            uint32_t* dst = &xs[r][c4];
            dst[0] = f2tf(v.x); dst[1] = f2tf(v.y);
            dst[2] = f2tf(v.z); dst[3] = f2tf(v.w);
        }
#pragma unroll
        for (int i = 0; i < 4; i++) {
            int lin = i * 256 + tid;
            int f  = lin & 127;
            int c4 = (lin >> 7) * 4;
            float4 v = *(const float4*)&W[f * 128 + kb + c4];
            ws[c4 + 0][f] = f2tf(v.x);
            ws[c4 + 1][f] = f2tf(v.y);
            ws[c4 + 2][f] = f2tf(v.z);
            ws[c4 + 3][f] = f2tf(v.w);
        }
        __syncthreads();
#pragma unroll
        for (int ks = 0; ks < 4; ks++) {
            int k0 = ks * 8;
            int r = warp * 16 + qid;
            uint32_t a0 = xs[r][k0 + tq];
            uint32_t a1 = xs[r + 8][k0 + tq];
            uint32_t a2 = xs[r][k0 + tq + 4];
            uint32_t a3 = xs[r + 8][k0 + tq + 4];
#pragma unroll
            for (int nt = 0; nt < 16; nt++) {
                uint32_t b0 = ws[k0 + tq][nt * 8 + qid];
                uint32_t b1 = ws[k0 + tq + 4][nt * 8 + qid];
                mma_tf32(c[nt], a0, a1, a2, a3, b0, b1);
            }
        }
        __syncthreads();
    }

    // epilogue: write h rows (fp16) + per-row attention dots (fp32)
    int r0 = row0 + warp * 16 + qid;
    int r1 = r0 + 8;
    float ps0[4] = {0,0,0,0}, ps1[4] = {0,0,0,0};
    float pd0[4] = {0,0,0,0}, pd1[4] = {0,0,0,0};
#pragma unroll
    for (int nt = 0; nt < 16; nt++) {
        int col = nt * 8 + 2 * tq;
        int head = nt >> 2;
        if (r0 < Nn)
            *(__half2*)&g_h16[(size_t)r0 * 128 + col] = __floats2half2_rn(c[nt][0], c[nt][1]);
        if (r1 < Nn)
            *(__half2*)&g_h16[(size_t)r1 * 128 + col] = __floats2half2_rn(c[nt][2], c[nt][3]);
        float as0 = att_src[col], as1 = att_src[col + 1];
        float ad0 = att_dst[col], ad1 = att_dst[col + 1];
        ps0[head] += c[nt][0] * as0 + c[nt][1] * as1;
        ps1[head] += c[nt][2] * as0 + c[nt][3] * as1;
        pd0[head] += c[nt][0] * ad0 + c[nt][1] * ad1;
        pd1[head] += c[nt][2] * ad0 + c[nt][3] * ad1;
    }
#pragma unroll
    for (int hd = 0; hd < 4; hd++) {
        ps0[hd] += __shfl_down_sync(0xFFFFFFFFu, ps0[hd], 1);
        ps0[hd] += __shfl_down_sync(0xFFFFFFFFu, ps0[hd], 2);
        ps1[hd] += __shfl_down_sync(0xFFFFFFFFu, ps1[hd], 1);
        ps1[hd] += __shfl_down_sync(0xFFFFFFFFu, ps1[hd], 2);
        pd0[hd] += __shfl_down_sync(0xFFFFFFFFu, pd0[hd], 1);
        pd0[hd] += __shfl_down_sync(0xFFFFFFFFu, pd0[hd], 2);
        pd1[hd] += __shfl_down_sync(0xFFFFFFFFu, pd1[hd], 1);
        pd1[hd] += __shfl_down_sync(0xFFFFFFFFu, pd1[hd], 2);
    }
    if (tq == 0) {
        if (r0 < Nn) {
#pragma unroll
            for (int hd = 0; hd < 4; hd++) {
                g_asrc[r0 * 4 + hd] = ps0[hd];
                g_adst[r0 * 4 + hd] = pd0[hd];
            }
        }
        if (r1 < Nn) {
#pragma unroll
            for (int hd = 0; hd < 4; hd++) {
                g_asrc[r1 * 4 + hd] = ps1[hd];
                g_adst[r1 * 4 + hd] = pd1[hd];
            }
        }
    }
}

// ---------------- CSR build: histogram / scan / scatter ----------------------
__global__ void hist_kernel(const int* __restrict__ ei) {
    int i = blockIdx.x * blockDim.x + threadIdx.x;
    if (i >= Ee) return;
    atomicAdd(&g_cnt[ei[Ee + i]], 1);
}

__global__ void scan1_kernel() {
    int i = blockIdx.x * 256 + threadIdx.x;
    int lane = threadIdx.x & 31, wid = threadIdx.x >> 5;
    int v = (i < Nn) ? g_cnt[i] : 0;
    int x = v;
#pragma unroll
    for (int o = 1; o < 32; o <<= 1) {
        int y = __shfl_up_sync(0xFFFFFFFFu, x, o);
        if (lane >= o) x += y;
    }
    __shared__ int wsum[8];
    if (lane == 31) wsum[wid] = x;
    __syncthreads();
    if (wid == 0 && lane < 8) {
        int t = wsum[lane];
        int xx = t;
#pragma unroll
        for (int o = 1; o < 8; o <<= 1) {
            int y = __shfl_up_sync(0xFFu, xx, o);
            if (lane >= o) xx += y;
        }
        wsum[lane] = xx - t;
    }
    __syncthreads();
    int incl = x + wsum[wid];
    if (i < Nn) g_row[i] = incl - v;
    if (threadIdx.x == 255) g_bsum[blockIdx.x] = incl;
}

__global__ void scan2_kernel() {
    int lane = threadIdx.x & 31, wid = threadIdx.x >> 5;
    int v = (threadIdx.x < NB) ? g_bsum[threadIdx.x] : 0;
    int x = v;
#pragma unroll
    for (int o = 1; o < 32; o <<= 1) {
        int y = __shfl_up_sync(0xFFFFFFFFu, x, o);
        if (lane >= o) x += y;
    }
    __shared__ int wsum[8];
    if (lane == 31) wsum[wid] = x;
    __syncthreads();
    if (wid == 0 && lane < 8) {
        int t = wsum[lane];
        int xx = t;
#pragma unroll
        for (int o = 1; o < 8; o <<= 1) {
            int y = __shfl_up_sync(0xFFu, xx, o);
            if (lane >= o) xx += y;
        }
        wsum[lane] = xx - t;
    }
    __syncthreads();
    if (threadIdx.x < NB) g_boff[threadIdx.x] = x + wsum[wid] - v;
}

// scan3 folded into consumers: row_start(n) = g_row[n] + g_boff[n>>8]
__global__ void scatter_kernel(const int* __restrict__ ei) {
    int i = blockIdx.x * blockDim.x + threadIdx.x;
    if (i >= Ee) return;
    int s = ei[i], d = ei[Ee + i];
    int pos = g_row[d] + __ldg(&g_boff[d >> 8]) + atomicAdd(&g_cur[d], 1);
    g_csr[pos] = s;
}

// ---------------- K6: gather-aggregate (fp16 h) + fused BN partial sums ------
__global__ void agg_kernel(const float* __restrict__ bias) {
    int lane = threadIdx.x & 31;
    int warp = (blockIdx.x * blockDim.x + threadIdx.x) >> 5;
    int nwarps = (gridDim.x * blockDim.x) >> 5;
    int hd = lane >> 3;

    __shared__ float sh_s[128];
    __shared__ float sh_q[128];
    if (threadIdx.x < 128) { sh_s[threadIdx.x] = 0.f; sh_q[threadIdx.x] = 0.f; }
    __syncthreads();

    float4 b = ((const float4*)bias)[lane];
    float bs_x = 0.f, bs_y = 0.f, bs_z = 0.f, bs_w = 0.f;
    float bq_x = 0.f, bq_y = 0.f, bq_z = 0.f, bq_w = 0.f;

    for (int w = warp; w < Nn; w += nwarps) {
        const float ad = g_adst[w * 4 + hd];
        float4 acc = make_float4(0.f, 0.f, 0.f, 0.f);
        float den = 0.f;

        // self loop
        {
            float e = g_asrc[w * 4 + hd] + ad;
            e = e > 0.f ? e : NEG * e;
            float ex = __expf(e);
            uint2 raw = *(const uint2*)&g_h16[(size_t)w * 128 + lane * 4];
            float2 f0 = __half22float2(*(__half2*)&raw.x);
            float2 f1 = __half22float2(*(__half2*)&raw.y);
            acc.x += ex * f0.x; acc.y += ex * f0.y;
            acc.z += ex * f1.x; acc.w += ex * f1.y;
            den += ex;
        }

        int start = g_row[w] + __ldg(&g_boff[w >> 8]);
        int len = g_cnt[w];
        for (int j = 0; j < len; j += 8) {
            int rem = len - j;
            int si[8];
#pragma unroll
            for (int u = 0; u < 8; u++) {
                int jj = (u < rem) ? j + u : j;
                si[u] = __ldg(&g_csr[start + jj]);
            }
            uint2 raw[8];
#pragma unroll
            for (int u = 0; u < 8; u++)
                raw[u] = *(const uint2*)&g_h16[(size_t)si[u] * 128 + lane * 4];
            float ev[8];
#pragma unroll
            for (int u = 0; u < 8; u++) {
                float e = g_asrc[si[u] * 4 + hd] + ad;
                e = e > 0.f ? e : NEG * e;
                float ex = __expf(e);
                ev[u] = (u < rem) ? ex : 0.f;
            }
#pragma unroll
            for (int u = 0; u < 8; u++) {
                float2 f0 = __half22float2(*(__half2*)&raw[u].x);
                float2 f1 = __half22float2(*(__half2*)&raw[u].y);
                acc.x += ev[u] * f0.x; acc.y += ev[u] * f0.y;
                acc.z += ev[u] * f1.x; acc.w += ev[u] * f1.y;
                den += ev[u];
            }
        }

        float rden = 1.f / (den + 1e-16f);
        float4 o;
        o.x = fmaxf(acc.x * rden + b.x, 0.f);
        o.y = fmaxf(acc.y * rden + b.y, 0.f);
        o.z = fmaxf(acc.z * rden + b.z, 0.f);
        o.w = fmaxf(acc.w * rden + b.w, 0.f);
        ((float4*)g_agg)[(size_t)w * 32 + lane] = o;

        bs_x += o.x; bs_y += o.y; bs_z += o.z; bs_w += o.w;
        bq_x += o.x * o.x; bq_y += o.y * o.y; bq_z += o.z * o.z; bq_w += o.w * o.w;
    }

    atomicAdd(&sh_s[lane * 4 + 0], bs_x);
    atomicAdd(&sh_s[lane * 4 + 1], bs_y);
    atomicAdd(&sh_s[lane * 4 + 2], bs_z);
    atomicAdd(&sh_s[lane * 4 + 3], bs_w);
    atomicAdd(&sh_q[lane * 4 + 0], bq_x);
    atomicAdd(&sh_q[lane * 4 + 1], bq_y);
    atomicAdd(&sh_q[lane * 4 + 2], bq_z);
    atomicAdd(&sh_q[lane * 4 + 3], bq_w);
    __syncthreads();
    if (threadIdx.x < 128) atomicAdd(&g_bns[threadIdx.x], sh_s[threadIdx.x]);
    else if (threadIdx.x < 256) atomicAdd(&g_bnq[threadIdx.x - 128], sh_q[threadIdx.x - 128]);
}

// ---------------- K8: BN normalize + write output ----------------------------
__global__ void bn_apply_kernel(const float* __restrict__ gamma,
                                const float* __restrict__ beta,
                                float* __restrict__ out) {
    int i = (blockIdx.x * blockDim.x + threadIdx.x) * 4;
    if (i >= Nn * 128) return;
    int f = i & 127;
    const float invn = 1.f / (float)Nn;
    float4 v = *(const float4*)&g_agg[i];
    float4 s = *(const float4*)&g_bns[f];
    float4 q = *(const float4*)&g_bnq[f];
    float4 gm = *(const float4*)&gamma[f];
    float4 bt = *(const float4*)&beta[f];
    float m0 = s.x * invn, m1 = s.y * invn, m2 = s.z * invn, m3 = s.w * invn;
    float4 o;
    o.x = (v.x - m0) * rsqrtf(q.x * invn - m0 * m0 + BN_EPS) * gm.x + bt.x;
    o.y = (v.y - m1) * rsqrtf(q.y * invn - m1 * m1 + BN_EPS) * gm.y + bt.y;
    o.z = (v.z - m2) * rsqrtf(q.z * invn - m2 * m2 + BN_EPS) * gm.z + bt.z;
    o.w = (v.w - m3) * rsqrtf(q.w * invn - m3 * m3 + BN_EPS) * gm.w + bt.w;
    *(float4*)&out[i] = o;
}

// ---------------- launch ------------------------------------------------------
extern "C" void kernel_launch(void* const* d_in, const int* in_sizes, int n_in,
                              void* d_out, int out_size) {
    (void)in_sizes; (void)n_in; (void)out_size;
    const float* x       = (const float*)d_in[0];
    const int*   ei      = (const int*)d_in[1];
    const float* W       = (const float*)d_in[2];
    const float* att_src = (const float*)d_in[3];
    const float* att_dst = (const float*)d_in[4];
    const float* bias    = (const float*)d_in[5];
    const float* gamma   = (const float*)d_in[6];
    const float* beta    = (const float*)d_in[7];

    cudaStream_t s2;
    cudaStreamCreateWithFlags(&s2, cudaStreamNonBlocking);
    cudaEvent_t eFork, eJoin;
    cudaEventCreateWithFlags(&eFork, cudaEventDisableTiming);
    cudaEventCreateWithFlags(&eJoin, cudaEventDisableTiming);

    cudaEventRecord(eFork, 0);
    cudaStreamWaitEvent(s2, eFork, 0);

    void* p;
    // CSR branch (stream s2) — overlapped with the GEMM
    cudaGetSymbolAddress(&p, g_cnt);  cudaMemsetAsync(p, 0, sizeof(int) * Nn, s2);
    cudaGetSymbolAddress(&p, g_cur);  cudaMemsetAsync(p, 0, sizeof(int) * Nn, s2);
    hist_kernel<<<(Ee + 255) / 256, 256, 0, s2>>>(ei);
    scan1_kernel<<<NB, 256, 0, s2>>>();
    scan2_kernel<<<1, 256, 0, s2>>>();
    scatter_kernel<<<(Ee + 255) / 256, 256, 0, s2>>>(ei);

    // main branch (stream 0)
    cudaGetSymbolAddress(&p, g_bns);  cudaMemsetAsync(p, 0, sizeof(float) * Ff);
    cudaGetSymbolAddress(&p, g_bnq);  cudaMemsetAsync(p, 0, sizeof(float) * Ff);
    gemm_att_kernel<<<(Nn + 127) / 128, 256>>>(x, W, att_src, att_dst);

    cudaEventRecord(eJoin, s2);
    cudaStreamWaitEvent(0, eJoin, 0);

    agg_kernel<<<592, 256>>>(bias);
    bn_apply_kernel<<<(Nn * 128 / 4 + 255) / 256, 256>>>(gamma, beta, (float*)d_out);

    cudaStreamDestroy(s2);
    cudaEventDestroy(eFork);
    cudaEventDestroy(eJoin);
}

// round 7
// speedup vs baseline: 2.3627x; 1.0005x over previous
#include <cuda_runtime.h>
#include <cuda_fp16.h>
#include <math.h>
#include <stdint.h>

#define Nn 50000
#define Ee 800000
#define Hh 4
#define Ff 128
#define NEG 0.2f
#define BN_EPS 1e-5f
#define CAP 64            // bucket capacity; P(deg>64) ~ 5e-19 per node

// ---------------- scratch (device globals) ----------------------------------
__device__ __align__(16) __half g_h16[(size_t)Nn * Ff];  // projected features, fp16
__device__ __align__(16) float g_asrc[Nn * Hh];          // per-node src attention logits
__device__ __align__(16) float g_adst[Nn * Hh];          // per-node dst attention logits
__device__ __align__(16) float g_agg[(size_t)Nn * Ff];   // aggregated (pre-BN) output
__device__ int   g_cur[Nn];                               // bucket cursor == in-degree
__device__ int   g_csr[(size_t)Nn * CAP];                 // per-dst edge buckets (src ids)
__device__ float g_bns[Ff];                               // BN sum per feature
__device__ float g_bnq[Ff];                               // BN sumsq per feature

__device__ __forceinline__ uint32_t f2tf(float f) {
    uint32_t u;
    asm("cvt.rna.tf32.f32 %0, %1;" : "=r"(u) : "f"(f));
    return u;
}

__device__ __forceinline__ void mma_tf32(float c[4], uint32_t a0, uint32_t a1,
                                         uint32_t a2, uint32_t a3,
                                         uint32_t b0, uint32_t b1) {
    asm volatile(
        "mma.sync.aligned.m16n8k8.row.col.f32.tf32.tf32.f32 "
        "{%0,%1,%2,%3}, {%4,%5,%6,%7}, {%8,%9}, {%0,%1,%2,%3};"
        : "+f"(c[0]), "+f"(c[1]), "+f"(c[2]), "+f"(c[3])
        : "r"(a0), "r"(a1), "r"(a2), "r"(a3), "r"(b0), "r"(b1));
}

// ---------------- K1: h = x @ W^T (tf32 tensor cores) + fused att logits -----
__global__ void gemm_att_kernel(const float* __restrict__ x,
                                const float* __restrict__ W,
                                const float* __restrict__ att_src,
                                const float* __restrict__ att_dst) {
    __shared__ uint32_t xs[128][36];
    __shared__ uint32_t ws[32][136];
    int tid = threadIdx.x;
    int warp = tid >> 5, lane = tid & 31;
    int qid = lane >> 2;
    int tq  = lane & 3;
    int row0 = blockIdx.x * 128;

    float c[16][4];
#pragma unroll
    for (int i = 0; i < 16; i++)
#pragma unroll
        for (int j = 0; j < 4; j++) c[i][j] = 0.f;

    for (int kb = 0; kb < 128; kb += 32) {
#pragma unroll
        for (int i = 0; i < 4; i++) {
            int lin = i * 256 + tid;
            int r = lin >> 3;
            int c4 = (lin & 7) * 4;
            int gr = row0 + r;
            float4 v = (gr < Nn) ? *(const float4*)&x[(size_t)gr * 128 + kb + c4]
                                 : make_float4(0.f, 0.f, 0.f, 0.f);
            uint32_t* dst = &xs[r][c4];
            dst[0] = f2tf(v.x); dst[1] = f2tf(v.y);
            dst[2] = f2tf(v.z); dst[3] = f2tf(v.w);
        }
#pragma unroll
        for (int i = 0; i < 4; i++) {
            int lin = i * 256 + tid;
            int f  = lin & 127;
            int c4 = (lin >> 7) * 4;
            float4 v = *(const float4*)&W[f * 128 + kb + c4];
            ws[c4 + 0][f] = f2tf(v.x);
            ws[c4 + 1][f] = f2tf(v.y);
            ws[c4 + 2][f] = f2tf(v.z);
            ws[c4 + 3][f] = f2tf(v.w);
        }
        __syncthreads();
#pragma unroll
        for (int ks = 0; ks < 4; ks++) {
            int k0 = ks * 8;
            int r = warp * 16 + qid;
            uint32_t a0 = xs[r][k0 + tq];
            uint32_t a1 = xs[r + 8][k0 + tq];
            uint32_t a2 = xs[r][k0 + tq + 4];
            uint32_t a3 = xs[r + 8][k0 + tq + 4];
#pragma unroll
            for (int nt = 0; nt < 16; nt++) {
                uint32_t b0 = ws[k0 + tq][nt * 8 + qid];
                uint32_t b1 = ws[k0 + tq + 4][nt * 8 + qid];
                mma_tf32(c[nt], a0, a1, a2, a3, b0, b1);
            }
        }
        __syncthreads();
    }

    // epilogue: write h rows (fp16) + per-row attention dots (fp32)
    int r0 = row0 + warp * 16 + qid;
    int r1 = r0 + 8;
    float ps0[4] = {0,0,0,0}, ps1[4] = {0,0,0,0};
    float pd0[4] = {0,0,0,0}, pd1[4] = {0,0,0,0};
#pragma unroll
    for (int nt = 0; nt < 16; nt++) {
        int col = nt * 8 + 2 * tq;
        int head = nt >> 2;
        if (r0 < Nn)
            *(__half2*)&g_h16[(size_t)r0 * 128 + col] = __floats2half2_rn(c[nt][0], c[nt][1]);
        if (r1 < Nn)
            *(__half2*)&g_h16[(size_t)r1 * 128 + col] = __floats2half2_rn(c[nt][2], c[nt][3]);
        float as0 = att_src[col], as1 = att_src[col + 1];
        float ad0 = att_dst[col], ad1 = att_dst[col + 1];
        ps0[head] += c[nt][0] * as0 + c[nt][1] * as1;
        ps1[head] += c[nt][2] * as0 + c[nt][3] * as1;
        pd0[head] += c[nt][0] * ad0 + c[nt][1] * ad1;
        pd1[head] += c[nt][2] * ad0 + c[nt][3] * ad1;
    }
#pragma unroll
    for (int hd = 0; hd < 4; hd++) {
        ps0[hd] += __shfl_down_sync(0xFFFFFFFFu, ps0[hd], 1);
        ps0[hd] += __shfl_down_sync(0xFFFFFFFFu, ps0[hd], 2);
        ps1[hd] += __shfl_down_sync(0xFFFFFFFFu, ps1[hd], 1);
        ps1[hd] += __shfl_down_sync(0xFFFFFFFFu, ps1[hd], 2);
        pd0[hd] += __shfl_down_sync(0xFFFFFFFFu, pd0[hd], 1);
        pd0[hd] += __shfl_down_sync(0xFFFFFFFFu, pd0[hd], 2);
        pd1[hd] += __shfl_down_sync(0xFFFFFFFFu, pd1[hd], 1);
        pd1[hd] += __shfl_down_sync(0xFFFFFFFFu, pd1[hd], 2);
    }
    if (tq == 0) {
        if (r0 < Nn) {
#pragma unroll
            for (int hd = 0; hd < 4; hd++) {
                g_asrc[r0 * 4 + hd] = ps0[hd];
                g_adst[r0 * 4 + hd] = pd0[hd];
            }
        }
        if (r1 < Nn) {
#pragma unroll
            for (int hd = 0; hd < 4; hd++) {
                g_asrc[r1 * 4 + hd] = ps1[hd];
                g_adst[r1 * 4 + hd] = pd1[hd];
            }
        }
    }
}

// ---------------- bucket scatter (replaces hist+scan+scatter) ----------------
// 4 edges per thread, int4 loads, 4 independent atomic/store chains.
__global__ void scatter_kernel(const int* __restrict__ ei) {
    int i4 = (blockIdx.x * blockDim.x + threadIdx.x) * 4;
    if (i4 >= Ee) return;
    int4 s4 = *(const int4*)&ei[i4];
    int4 d4 = *(const int4*)&ei[Ee + i4];
    int p0 = atomicAdd(&g_cur[d4.x], 1);
    int p1 = atomicAdd(&g_cur[d4.y], 1);
    int p2 = atomicAdd(&g_cur[d4.z], 1);
    int p3 = atomicAdd(&g_cur[d4.w], 1);
    if (p0 < CAP) g_csr[(size_t)d4.x * CAP + p0] = s4.x;
    if (p1 < CAP) g_csr[(size_t)d4.y * CAP + p1] = s4.y;
    if (p2 < CAP) g_csr[(size_t)d4.z * CAP + p2] = s4.z;
    if (p3 < CAP) g_csr[(size_t)d4.w * CAP + p3] = s4.w;
}

// ---------------- K6: gather-aggregate (fp16 h) + fused BN partial sums ------
__global__ void agg_kernel(const float* __restrict__ bias) {
    int lane = threadIdx.x & 31;
    int warp = (blockIdx.x * blockDim.x + threadIdx.x) >> 5;
    int nwarps = (gridDim.x * blockDim.x) >> 5;
    int hd = lane >> 3;

    __shared__ float sh_s[128];
    __shared__ float sh_q[128];
    if (threadIdx.x < 128) { sh_s[threadIdx.x] = 0.f; sh_q[threadIdx.x] = 0.f; }
    __syncthreads();

    float4 b = ((const float4*)bias)[lane];
    float bs_x = 0.f, bs_y = 0.f, bs_z = 0.f, bs_w = 0.f;
    float bq_x = 0.f, bq_y = 0.f, bq_z = 0.f, bq_w = 0.f;

    for (int w = warp; w < Nn; w += nwarps) {
        const float ad = g_adst[w * 4 + hd];
        float4 acc = make_float4(0.f, 0.f, 0.f, 0.f);
        float den = 0.f;

        // self loop
        {
            float e = g_asrc[w * 4 + hd] + ad;
            e = e > 0.f ? e : NEG * e;
            float ex = __expf(e);
            uint2 raw = *(const uint2*)&g_h16[(size_t)w * 128 + lane * 4];
            float2 f0 = __half22float2(*(__half2*)&raw.x);
            float2 f1 = __half22float2(*(__half2*)&raw.y);
            acc.x += ex * f0.x; acc.y += ex * f0.y;
            acc.z += ex * f1.x; acc.w += ex * f1.y;
            den += ex;
        }

        int len = g_cur[w];
        len = len < CAP ? len : CAP;
        const int* bucket = &g_csr[(size_t)w * CAP];
        for (int j = 0; j < len; j += 8) {
            int rem = len - j;
            int si[8];
#pragma unroll
            for (int u = 0; u < 8; u++) {
                int jj = (u < rem) ? j + u : j;
                si[u] = __ldg(&bucket[jj]);
            }
            uint2 raw[8];
#pragma unroll
            for (int u = 0; u < 8; u++)
                raw[u] = *(const uint2*)&g_h16[(size_t)si[u] * 128 + lane * 4];
            float ev[8];
#pragma unroll
            for (int u = 0; u < 8; u++) {
                float e = g_asrc[si[u] * 4 + hd] + ad;
                e = e > 0.f ? e : NEG * e;
                float ex = __expf(e);
                ev[u] = (u < rem) ? ex : 0.f;
            }
#pragma unroll
            for (int u = 0; u < 8; u++) {
                float2 f0 = __half22float2(*(__half2*)&raw[u].x);
                float2 f1 = __half22float2(*(__half2*)&raw[u].y);
                acc.x += ev[u] * f0.x; acc.y += ev[u] * f0.y;
                acc.z += ev[u] * f1.x; acc.w += ev[u] * f1.y;
                den += ev[u];
            }
        }

        float rden = 1.f / (den + 1e-16f);
        float4 o;
        o.x = fmaxf(acc.x * rden + b.x, 0.f);
        o.y = fmaxf(acc.y * rden + b.y, 0.f);
        o.z = fmaxf(acc.z * rden + b.z, 0.f);
        o.w = fmaxf(acc.w * rden + b.w, 0.f);
        ((float4*)g_agg)[(size_t)w * 32 + lane] = o;

        bs_x += o.x; bs_y += o.y; bs_z += o.z; bs_w += o.w;
        bq_x += o.x * o.x; bq_y += o.y * o.y; bq_z += o.z * o.z; bq_w += o.w * o.w;
    }

    atomicAdd(&sh_s[lane * 4 + 0], bs_x);
    atomicAdd(&sh_s[lane * 4 + 1], bs_y);
    atomicAdd(&sh_s[lane * 4 + 2], bs_z);
    atomicAdd(&sh_s[lane * 4 + 3], bs_w);
    atomicAdd(&sh_q[lane * 4 + 0], bq_x);
    atomicAdd(&sh_q[lane * 4 + 1], bq_y);
    atomicAdd(&sh_q[lane * 4 + 2], bq_z);
    atomicAdd(&sh_q[lane * 4 + 3], bq_w);
    __syncthreads();
    if (threadIdx.x < 128) atomicAdd(&g_bns[threadIdx.x], sh_s[threadIdx.x]);
    else if (threadIdx.x < 256) atomicAdd(&g_bnq[threadIdx.x - 128], sh_q[threadIdx.x - 128]);
}

// ---------------- K8: BN normalize + write output ----------------------------
__global__ void bn_apply_kernel(const float* __restrict__ gamma,
                                const float* __restrict__ beta,
                                float* __restrict__ out) {
    int i = (blockIdx.x * blockDim.x + threadIdx.x) * 4;
    if (i >= Nn * 128) return;
    int f = i & 127;
    const float invn = 1.f / (float)Nn;
    float4 v = *(const float4*)&g_agg[i];
    float4 s = *(const float4*)&g_bns[f];
    float4 q = *(const float4*)&g_bnq[f];
    float4 gm = *(const float4*)&gamma[f];
    float4 bt = *(const float4*)&beta[f];
    float m0 = s.x * invn, m1 = s.y * invn, m2 = s.z * invn, m3 = s.w * invn;
    float4 o;
    o.x = (v.x - m0) * rsqrtf(q.x * invn - m0 * m0 + BN_EPS) * gm.x + bt.x;
    o.y = (v.y - m1) * rsqrtf(q.y * invn - m1 * m1 + BN_EPS) * gm.y + bt.y;
    o.z = (v.z - m2) * rsqrtf(q.z * invn - m2 * m2 + BN_EPS) * gm.z + bt.z;
    o.w = (v.w - m3) * rsqrtf(q.w * invn - m3 * m3 + BN_EPS) * gm.w + bt.w;
    *(float4*)&out[i] = o;
}

// ---------------- launch ------------------------------------------------------
extern "C" void kernel_launch(void* const* d_in, const int* in_sizes, int n_in,
                              void* d_out, int out_size) {
    (void)in_sizes; (void)n_in; (void)out_size;
    const float* x       = (const float*)d_in[0];
    const int*   ei      = (const int*)d_in[1];
    const float* W       = (const float*)d_in[2];
    const float* att_src = (const float*)d_in[3];
    const float* att_dst = (const float*)d_in[4];
    const float* bias    = (const float*)d_in[5];
    const float* gamma   = (const float*)d_in[6];
    const float* beta    = (const float*)d_in[7];

    cudaStream_t s2;
    cudaStreamCreateWithFlags(&s2, cudaStreamNonBlocking);
    cudaEvent_t eFork, eJoin;
    cudaEventCreateWithFlags(&eFork, cudaEventDisableTiming);
    cudaEventCreateWithFlags(&eJoin, cudaEventDisableTiming);

    cudaEventRecord(eFork, 0);
    cudaStreamWaitEvent(s2, eFork, 0);

    void* p;
    // bucket branch (stream s2) — hidden under the GEMM
    cudaGetSymbolAddress(&p, g_cur);  cudaMemsetAsync(p, 0, sizeof(int) * Nn, s2);
    scatter_kernel<<<(Ee / 4 + 255) / 256, 256, 0, s2>>>(ei);

    // main branch (stream 0)
    cudaGetSymbolAddress(&p, g_bns);  cudaMemsetAsync(p, 0, sizeof(float) * Ff);
    cudaGetSymbolAddress(&p, g_bnq);  cudaMemsetAsync(p, 0, sizeof(float) * Ff);
    gemm_att_kernel<<<(Nn + 127) / 128, 256>>>(x, W, att_src, att_dst);

    cudaEventRecord(eJoin, s2);
    cudaStreamWaitEvent(0, eJoin, 0);

    agg_kernel<<<592, 256>>>(bias);
    bn_apply_kernel<<<(Nn * 128 / 4 + 255) / 256, 256>>>(gamma, beta, (float*)d_out);

    cudaStreamDestroy(s2);
    cudaEventDestroy(eFork);
    cudaEventDestroy(eJoin);
}

// round 9
// speedup vs baseline: 2.4378x; 1.0318x over previous
#include <cuda_runtime.h>
#include <cuda_fp16.h>
#include <math.h>
#include <stdint.h>

#define Nn 50000
#define Ee 800000
#define Hh 4
#define Ff 128
#define NEG 0.2f
#define BN_EPS 1e-5f
#define CAP 64            // bucket capacity; P(deg>64) ~ 5e-19 per node

// ---------------- scratch (device globals) ----------------------------------
__device__ __align__(16) __half g_h16[(size_t)Nn * Ff];  // projected features, fp16
__device__ __align__(16) float g_asrc[Nn * Hh];          // per-node src attention logits
__device__ __align__(16) float g_adst[Nn * Hh];          // per-node dst attention logits
__device__ __align__(16) float g_agg[(size_t)Nn * Ff];   // aggregated (pre-BN) output
__device__ int   g_cur[Nn];                               // bucket cursor == in-degree
__device__ __align__(16) int g_csr[(size_t)Nn * CAP];    // per-dst edge buckets (src ids)
__device__ float g_bns[Ff];                               // BN sum per feature
__device__ float g_bnq[Ff];                               // BN sumsq per feature

__device__ __forceinline__ uint32_t f2tf(float f) {
    uint32_t u;
    asm("cvt.rna.tf32.f32 %0, %1;" : "=r"(u) : "f"(f));
    return u;
}

__device__ __forceinline__ void mma_tf32(float c[4], uint32_t a0, uint32_t a1,
                                         uint32_t a2, uint32_t a3,
                                         uint32_t b0, uint32_t b1) {
    asm volatile(
        "mma.sync.aligned.m16n8k8.row.col.f32.tf32.tf32.f32 "
        "{%0,%1,%2,%3}, {%4,%5,%6,%7}, {%8,%9}, {%0,%1,%2,%3};"
        : "+f"(c[0]), "+f"(c[1]), "+f"(c[2]), "+f"(c[3])
        : "r"(a0), "r"(a1), "r"(a2), "r"(a3), "r"(b0), "r"(b1));
}

// ---------------- K1: h = x @ W^T (tf32 tensor cores) + fused att logits -----
__global__ void gemm_att_kernel(const float* __restrict__ x,
                                const float* __restrict__ W,
                                const float* __restrict__ att_src,
                                const float* __restrict__ att_dst) {
    __shared__ uint32_t xs[128][36];
    __shared__ uint32_t ws[32][136];
    int tid = threadIdx.x;
    int warp = tid >> 5, lane = tid & 31;
    int qid = lane >> 2;
    int tq  = lane & 3;
    int row0 = blockIdx.x * 128;

    float c[16][4];
#pragma unroll
    for (int i = 0; i < 16; i++)
#pragma unroll
        for (int j = 0; j < 4; j++) c[i][j] = 0.f;

    for (int kb = 0; kb < 128; kb += 32) {
#pragma unroll
        for (int i = 0; i < 4; i++) {
            int lin = i * 256 + tid;
            int r = lin >> 3;
            int c4 = (lin & 7) * 4;
            int gr = row0 + r;
            float4 v = (gr < Nn) ? *(const float4*)&x[(size_t)gr * 128 + kb + c4]
                                 : make_float4(0.f, 0.f, 0.f, 0.f);
            uint32_t* dst = &xs[r][c4];
            dst[0] = f2tf(v.x); dst[1] = f2tf(v.y);
            dst[2] = f2tf(v.z); dst[3] = f2tf(v.w);
        }
#pragma unroll
        for (int i = 0; i < 4; i++) {
            int lin = i * 256 + tid;
            int f  = lin & 127;
            int c4 = (lin >> 7) * 4;
            float4 v = *(const float4*)&W[f * 128 + kb + c4];
            ws[c4 + 0][f] = f2tf(v.x);
            ws[c4 + 1][f] = f2tf(v.y);
            ws[c4 + 2][f] = f2tf(v.z);
            ws[c4 + 3][f] = f2tf(v.w);
        }
        __syncthreads();
#pragma unroll
        for (int ks = 0; ks < 4; ks++) {
            int k0 = ks * 8;
            int r = warp * 16 + qid;
            uint32_t a0 = xs[r][k0 + tq];
            uint32_t a1 = xs[r + 8][k0 + tq];
            uint32_t a2 = xs[r][k0 + tq + 4];
            uint32_t a3 = xs[r + 8][k0 + tq + 4];
#pragma unroll
            for (int nt = 0; nt < 16; nt++) {
                uint32_t b0 = ws[k0 + tq][nt * 8 + qid];
                uint32_t b1 = ws[k0 + tq + 4][nt * 8 + qid];
                mma_tf32(c[nt], a0, a1, a2, a3, b0, b1);
            }
        }
        __syncthreads();
    }

    // epilogue: write h rows (fp16) + per-row attention dots (fp32)
    int r0 = row0 + warp * 16 + qid;
    int r1 = r0 + 8;
    float ps0[4] = {0,0,0,0}, ps1[4] = {0,0,0,0};
    float pd0[4] = {0,0,0,0}, pd1[4] = {0,0,0,0};
#pragma unroll
    for (int nt = 0; nt < 16; nt++) {
        int col = nt * 8 + 2 * tq;
        int head = nt >> 2;
        if (r0 < Nn)
            *(__half2*)&g_h16[(size_t)r0 * 128 + col] = __floats2half2_rn(c[nt][0], c[nt][1]);
        if (r1 < Nn)
            *(__half2*)&g_h16[(size_t)r1 * 128 + col] = __floats2half2_rn(c[nt][2], c[nt][3]);
        float as0 = att_src[col], as1 = att_src[col + 1];
        float ad0 = att_dst[col], ad1 = att_dst[col + 1];
        ps0[head] += c[nt][0] * as0 + c[nt][1] * as1;
        ps1[head] += c[nt][2] * as0 + c[nt][3] * as1;
        pd0[head] += c[nt][0] * ad0 + c[nt][1] * ad1;
        pd1[head] += c[nt][2] * ad0 + c[nt][3] * ad1;
    }
#pragma unroll
    for (int hd = 0; hd < 4; hd++) {
        ps0[hd] += __shfl_down_sync(0xFFFFFFFFu, ps0[hd], 1);
        ps0[hd] += __shfl_down_sync(0xFFFFFFFFu, ps0[hd], 2);
        ps1[hd] += __shfl_down_sync(0xFFFFFFFFu, ps1[hd], 1);
        ps1[hd] += __shfl_down_sync(0xFFFFFFFFu, ps1[hd], 2);
        pd0[hd] += __shfl_down_sync(0xFFFFFFFFu, pd0[hd], 1);
        pd0[hd] += __shfl_down_sync(0xFFFFFFFFu, pd0[hd], 2);
        pd1[hd] += __shfl_down_sync(0xFFFFFFFFu, pd1[hd], 1);
        pd1[hd] += __shfl_down_sync(0xFFFFFFFFu, pd1[hd], 2);
    }
    if (tq == 0) {
        if (r0 < Nn) {
#pragma unroll
            for (int hd = 0; hd < 4; hd++) {
                g_asrc[r0 * 4 + hd] = ps0[hd];
                g_adst[r0 * 4 + hd] = pd0[hd];
            }
        }
        if (r1 < Nn) {
#pragma unroll
            for (int hd = 0; hd < 4; hd++) {
                g_asrc[r1 * 4 + hd] = ps1[hd];
                g_adst[r1 * 4 + hd] = pd1[hd];
            }
        }
    }
}

// ---------------- bucket scatter ---------------------------------------------
__global__ void scatter_kernel(const int* __restrict__ ei) {
    int i4 = (blockIdx.x * blockDim.x + threadIdx.x) * 4;
    if (i4 >= Ee) return;
    int4 s4 = *(const int4*)&ei[i4];
    int4 d4 = *(const int4*)&ei[Ee + i4];
    int p0 = atomicAdd(&g_cur[d4.x], 1);
    int p1 = atomicAdd(&g_cur[d4.y], 1);
    int p2 = atomicAdd(&g_cur[d4.z], 1);
    int p3 = atomicAdd(&g_cur[d4.w], 1);
    if (p0 < CAP) g_csr[(size_t)d4.x * CAP + p0] = s4.x;
    if (p1 < CAP) g_csr[(size_t)d4.y * CAP + p1] = s4.y;
    if (p2 < CAP) g_csr[(size_t)d4.z * CAP + p2] = s4.z;
    if (p3 < CAP) g_csr[(size_t)d4.w * CAP + p3] = s4.w;
}

// ---------------- K6: dual-node gather-aggregate + fused BN ------------------
// Each warp interleaves TWO independent nodes (A = w, B = w + nwarps),
// 4-edge int4-indexed batches each: two independent bucket->gather chains
// in flight, halving exposed latency vs one 8-deep chain.
__global__ __launch_bounds__(256) void agg_kernel(const float* __restrict__ bias) {
    int lane = threadIdx.x & 31;
    int warp = (blockIdx.x * blockDim.x + threadIdx.x) >> 5;
    int nwarps = (gridDim.x * blockDim.x) >> 5;
    int hd = lane >> 3;

    __shared__ float sh_s[128];
    __shared__ float sh_q[128];
    if (threadIdx.x < 128) { sh_s[threadIdx.x] = 0.f; sh_q[threadIdx.x] = 0.f; }
    __syncthreads();

    float4 b = ((const float4*)bias)[lane];
    float bs_x = 0.f, bs_y = 0.f, bs_z = 0.f, bs_w = 0.f;
    float bq_x = 0.f, bq_y = 0.f, bq_z = 0.f, bq_w = 0.f;

    for (int wA = warp; wA < Nn; wA += 2 * nwarps) {
        int wB = wA + nwarps;
        bool hasB = (wB < Nn);
        int wBs = hasB ? wB : wA;          // safe index for all B-side accesses

        int lenA = min(g_cur[wA], CAP);
        int lenB = hasB ? min(g_cur[wBs], CAP) : 0;
        float adA = g_adst[wA * 4 + hd];
        float adB = g_adst[wBs * 4 + hd];

        float4 accA = make_float4(0.f, 0.f, 0.f, 0.f);
        float4 accB = make_float4(0.f, 0.f, 0.f, 0.f);
        float denA = 0.f, denB = 0.f;

        // self loops (both issued before waiting)
        {
            uint2 rA = *(const uint2*)&g_h16[(size_t)wA * 128 + lane * 4];
            uint2 rB = *(const uint2*)&g_h16[(size_t)wBs * 128 + lane * 4];
            float eA = g_asrc[wA * 4 + hd] + adA;
            float eB = g_asrc[wBs * 4 + hd] + adB;
            eA = fmaxf(eA, NEG * eA);
            eB = fmaxf(eB, NEG * eB);
            float xA = __expf(eA);
            float xB = hasB ? __expf(eB) : 0.f;
            float2 a0 = __half22float2(*(__half2*)&rA.x);
            float2 a1 = __half22float2(*(__half2*)&rA.y);
            float2 b0 = __half22float2(*(__half2*)&rB.x);
            float2 b1 = __half22float2(*(__half2*)&rB.y);
            accA.x += xA * a0.x; accA.y += xA * a0.y;
            accA.z += xA * a1.x; accA.w += xA * a1.y;
            accB.x += xB * b0.x; accB.y += xB * b0.y;
            accB.z += xB * b1.x; accB.w += xB * b1.y;
            denA += xA; denB += xB;
        }

        const int4* bktA = (const int4*)&g_csr[(size_t)wA * CAP];
        const int4* bktB = (const int4*)&g_csr[(size_t)wBs * CAP];
        int lenMax = max(lenA, lenB);

        for (int j = 0; j < lenMax; j += 4) {
            int4 iA = __ldg(&bktA[j >> 2]);   // in-bounds: j < CAP always
            int4 iB = __ldg(&bktB[j >> 2]);
            int sA[4] = {iA.x, iA.y, iA.z, iA.w};
            int sB[4] = {iB.x, iB.y, iB.z, iB.w};
#pragma unroll
            for (int u = 0; u < 4; u++) {
                sA[u] = (j + u < lenA) ? sA[u] : wA;   // clamp garbage slots
                sB[u] = (j + u < lenB) ? sB[u] : wBs;
            }
            uint2 rA[4], rB[4];
#pragma unroll
            for (int u = 0; u < 4; u++) {
                rA[u] = *(const uint2*)&g_h16[(size_t)sA[u] * 128 + lane * 4];
                rB[u] = *(const uint2*)&g_h16[(size_t)sB[u] * 128 + lane * 4];
            }
            float evA[4], evB[4];
#pragma unroll
            for (int u = 0; u < 4; u++) {
                float eA = g_asrc[sA[u] * 4 + hd] + adA;
                float eB = g_asrc[sB[u] * 4 + hd] + adB;
                eA = fmaxf(eA, NEG * eA);
                eB = fmaxf(eB, NEG * eB);
                float xA = __expf(eA);
                float xB = __expf(eB);
                evA[u] = (j + u < lenA) ? xA : 0.f;
                evB[u] = (j + u < lenB) ? xB : 0.f;
            }
#pragma unroll
            for (int u = 0; u < 4; u++) {
                float2 fa0 = __half22float2(*(__half2*)&rA[u].x);
                float2 fa1 = __half22float2(*(__half2*)&rA[u].y);
                float2 fb0 = __half22float2(*(__half2*)&rB[u].x);
                float2 fb1 = __half22float2(*(__half2*)&rB[u].y);
                accA.x += evA[u] * fa0.x; accA.y += evA[u] * fa0.y;
                accA.z += evA[u] * fa1.x; accA.w += evA[u] * fa1.y;
                accB.x += evB[u] * fb0.x; accB.y += evB[u] * fb0.y;
                accB.z += evB[u] * fb1.x; accB.w += evB[u] * fb1.y;
                denA += evA[u]; denB += evB[u];
            }
        }

        // finalize A
        {
            float rden = 1.f / (denA + 1e-16f);
            float4 o;
            o.x = fmaxf(accA.x * rden + b.x, 0.f);
            o.y = fmaxf(accA.y * rden + b.y, 0.f);
            o.z = fmaxf(accA.z * rden + b.z, 0.f);
            o.w = fmaxf(accA.w * rden + b.w, 0.f);
            ((float4*)g_agg)[(size_t)wA * 32 + lane] = o;
            bs_x += o.x; bs_y += o.y; bs_z += o.z; bs_w += o.w;
            bq_x += o.x * o.x; bq_y += o.y * o.y; bq_z += o.z * o.z; bq_w += o.w * o.w;
        }
        // finalize B
        if (hasB) {
            float rden = 1.f / (denB + 1e-16f);
            float4 o;
            o.x = fmaxf(accB.x * rden + b.x, 0.f);
            o.y = fmaxf(accB.y * rden + b.y, 0.f);
            o.z = fmaxf(accB.z * rden + b.z, 0.f);
            o.w = fmaxf(accB.w * rden + b.w, 0.f);
            ((float4*)g_agg)[(size_t)wB * 32 + lane] = o;
            bs_x += o.x; bs_y += o.y; bs_z += o.z; bs_w += o.w;
            bq_x += o.x * o.x; bq_y += o.y * o.y; bq_z += o.z * o.z; bq_w += o.w * o.w;
        }
    }

    atomicAdd(&sh_s[lane * 4 + 0], bs_x);
    atomicAdd(&sh_s[lane * 4 + 1], bs_y);
    atomicAdd(&sh_s[lane * 4 + 2], bs_z);
    atomicAdd(&sh_s[lane * 4 + 3], bs_w);
    atomicAdd(&sh_q[lane * 4 + 0], bq_x);
    atomicAdd(&sh_q[lane * 4 + 1], bq_y);
    atomicAdd(&sh_q[lane * 4 + 2], bq_z);
    atomicAdd(&sh_q[lane * 4 + 3], bq_w);
    __syncthreads();
    if (threadIdx.x < 128) atomicAdd(&g_bns[threadIdx.x], sh_s[threadIdx.x]);
    else if (threadIdx.x < 256) atomicAdd(&g_bnq[threadIdx.x - 128], sh_q[threadIdx.x - 128]);
}

// ---------------- K8: BN normalize + write output ----------------------------
__global__ void bn_apply_kernel(const float* __restrict__ gamma,
                                const float* __restrict__ beta,
                                float* __restrict__ out) {
    int i = (blockIdx.x * blockDim.x + threadIdx.x) * 4;
    if (i >= Nn * 128) return;
    int f = i & 127;
    const float invn = 1.f / (float)Nn;
    float4 v = *(const float4*)&g_agg[i];
    float4 s = *(const float4*)&g_bns[f];
    float4 q = *(const float4*)&g_bnq[f];
    float4 gm = *(const float4*)&gamma[f];
    float4 bt = *(const float4*)&beta[f];
    float m0 = s.x * invn, m1 = s.y * invn, m2 = s.z * invn, m3 = s.w * invn;
    float4 o;
    o.x = (v.x - m0) * rsqrtf(q.x * invn - m0 * m0 + BN_EPS) * gm.x + bt.x;
    o.y = (v.y - m1) * rsqrtf(q.y * invn - m1 * m1 + BN_EPS) * gm.y + bt.y;
    o.z = (v.z - m2) * rsqrtf(q.z * invn - m2 * m2 + BN_EPS) * gm.z + bt.z;
    o.w = (v.w - m3) * rsqrtf(q.w * invn - m3 * m3 + BN_EPS) * gm.w + bt.w;
    *(float4*)&out[i] = o;
}

// ---------------- launch ------------------------------------------------------
extern "C" void kernel_launch(void* const* d_in, const int* in_sizes, int n_in,
                              void* d_out, int out_size) {
    (void)in_sizes; (void)n_in; (void)out_size;
    const float* x       = (const float*)d_in[0];
    const int*   ei      = (const int*)d_in[1];
    const float* W       = (const float*)d_in[2];
    const float* att_src = (const float*)d_in[3];
    const float* att_dst = (const float*)d_in[4];
    const float* bias    = (const float*)d_in[5];
    const float* gamma   = (const float*)d_in[6];
    const float* beta    = (const float*)d_in[7];

    cudaStream_t s2;
    cudaStreamCreateWithFlags(&s2, cudaStreamNonBlocking);
    cudaEvent_t eFork, eJoin;
    cudaEventCreateWithFlags(&eFork, cudaEventDisableTiming);
    cudaEventCreateWithFlags(&eJoin, cudaEventDisableTiming);

    cudaEventRecord(eFork, 0);
    cudaStreamWaitEvent(s2, eFork, 0);

    void* p;
    // side branch (stream s2) — hidden under the GEMM
    cudaGetSymbolAddress(&p, g_cur);  cudaMemsetAsync(p, 0, sizeof(int) * Nn, s2);
    cudaGetSymbolAddress(&p, g_bns);  cudaMemsetAsync(p, 0, sizeof(float) * Ff, s2);
    cudaGetSymbolAddress(&p, g_bnq);  cudaMemsetAsync(p, 0, sizeof(float) * Ff, s2);
    scatter_kernel<<<(Ee / 4 + 255) / 256, 256, 0, s2>>>(ei);

    // main branch (stream 0): pure compute
    gemm_att_kernel<<<(Nn + 127) / 128, 256>>>(x, W, att_src, att_dst);

    cudaEventRecord(eJoin, s2);
    cudaStreamWaitEvent(0, eJoin, 0);

    agg_kernel<<<592, 256>>>(bias);
    bn_apply_kernel<<<(Nn * 128 / 4 + 255) / 256, 256>>>(gamma, beta, (float*)d_out);

    cudaStreamDestroy(s2);
    cudaEventDestroy(eFork);
    cudaEventDestroy(eJoin);
}

// round 10
// speedup vs baseline: 2.5336x; 1.0393x over previous
#include <cuda_runtime.h>
#include <cuda_fp16.h>
#include <math.h>
#include <stdint.h>

#define Nn 50000
#define Ee 800000
#define Hh 4
#define Ff 128
#define NEG 0.2f
#define BN_EPS 1e-5f
#define CAP 64            // bucket capacity; P(deg>64) ~ 5e-19 per node

// ---------------- scratch (device globals) ----------------------------------
__device__ __align__(16) __half g_h16[(size_t)Nn * Ff];  // projected features, fp16
__device__ __align__(16) float g_asrc[Nn * Hh];          // per-node src attention logits
__device__ __align__(16) float g_adst[Nn * Hh];          // per-node dst attention logits
__device__ __align__(16) float g_agg[(size_t)Nn * Ff];   // aggregated (pre-BN) output
__device__ int   g_cur[Nn];                               // bucket cursor == in-degree
__device__ __align__(16) int g_csr[(size_t)Nn * CAP];    // per-dst edge buckets (src ids)
__device__ float g_bns[Ff];                               // BN sum per feature
__device__ float g_bnq[Ff];                               // BN sumsq per feature

__device__ __forceinline__ uint32_t f2tf(float f) {
    uint32_t u;
    asm("cvt.rna.tf32.f32 %0, %1;" : "=r"(u) : "f"(f));
    return u;
}

__device__ __forceinline__ void mma_tf32(float c[4], uint32_t a0, uint32_t a1,
                                         uint32_t a2, uint32_t a3,
                                         uint32_t b0, uint32_t b1) {
    asm volatile(
        "mma.sync.aligned.m16n8k8.row.col.f32.tf32.tf32.f32 "
        "{%0,%1,%2,%3}, {%4,%5,%6,%7}, {%8,%9}, {%0,%1,%2,%3};"
        : "+f"(c[0]), "+f"(c[1]), "+f"(c[2]), "+f"(c[3])
        : "r"(a0), "r"(a1), "r"(a2), "r"(a3), "r"(b0), "r"(b1));
}

// ---------------- K1: h = x @ W^T (tf32 tensor cores) + fused att logits -----
__global__ void gemm_att_kernel(const float* __restrict__ x,
                                const float* __restrict__ W,
                                const float* __restrict__ att_src,
                                const float* __restrict__ att_dst) {
    __shared__ uint32_t xs[128][36];
    __shared__ uint32_t ws[32][136];
    int tid = threadIdx.x;
    int warp = tid >> 5, lane = tid & 31;
    int qid = lane >> 2;
    int tq  = lane & 3;
    int row0 = blockIdx.x * 128;

    float c[16][4];
#pragma unroll
    for (int i = 0; i < 16; i++)
#pragma unroll
        for (int j = 0; j < 4; j++) c[i][j] = 0.f;

    for (int kb = 0; kb < 128; kb += 32) {
#pragma unroll
        for (int i = 0; i < 4; i++) {
            int lin = i * 256 + tid;
            int r = lin >> 3;
            int c4 = (lin & 7) * 4;
            int gr = row0 + r;
            float4 v = (gr < Nn) ? *(const float4*)&x[(size_t)gr * 128 + kb + c4]
                                 : make_float4(0.f, 0.f, 0.f, 0.f);
            uint32_t* dst = &xs[r][c4];
            dst[0] = f2tf(v.x); dst[1] = f2tf(v.y);
            dst[2] = f2tf(v.z); dst[3] = f2tf(v.w);
        }
#pragma unroll
        for (int i = 0; i < 4; i++) {
            int lin = i * 256 + tid;
            int f  = lin & 127;
            int c4 = (lin >> 7) * 4;
            float4 v = *(const float4*)&W[f * 128 + kb + c4];
            ws[c4 + 0][f] = f2tf(v.x);
            ws[c4 + 1][f] = f2tf(v.y);
            ws[c4 + 2][f] = f2tf(v.z);
            ws[c4 + 3][f] = f2tf(v.w);
        }
        __syncthreads();
#pragma unroll
        for (int ks = 0; ks < 4; ks++) {
            int k0 = ks * 8;
            int r = warp * 16 + qid;
            uint32_t a0 = xs[r][k0 + tq];
            uint32_t a1 = xs[r + 8][k0 + tq];
            uint32_t a2 = xs[r][k0 + tq + 4];
            uint32_t a3 = xs[r + 8][k0 + tq + 4];
#pragma unroll
            for (int nt = 0; nt < 16; nt++) {
                uint32_t b0 = ws[k0 + tq][nt * 8 + qid];
                uint32_t b1 = ws[k0 + tq + 4][nt * 8 + qid];
                mma_tf32(c[nt], a0, a1, a2, a3, b0, b1);
            }
        }
        __syncthreads();
    }

    // epilogue: write h rows (fp16) + per-row attention dots (fp32)
    int r0 = row0 + warp * 16 + qid;
    int r1 = r0 + 8;
    float ps0[4] = {0,0,0,0}, ps1[4] = {0,0,0,0};
    float pd0[4] = {0,0,0,0}, pd1[4] = {0,0,0,0};
#pragma unroll
    for (int nt = 0; nt < 16; nt++) {
        int col = nt * 8 + 2 * tq;
        int head = nt >> 2;
        if (r0 < Nn)
            *(__half2*)&g_h16[(size_t)r0 * 128 + col] = __floats2half2_rn(c[nt][0], c[nt][1]);
        if (r1 < Nn)
            *(__half2*)&g_h16[(size_t)r1 * 128 + col] = __floats2half2_rn(c[nt][2], c[nt][3]);
        float as0 = att_src[col], as1 = att_src[col + 1];
        float ad0 = att_dst[col], ad1 = att_dst[col + 1];
        ps0[head] += c[nt][0] * as0 + c[nt][1] * as1;
        ps1[head] += c[nt][2] * as0 + c[nt][3] * as1;
        pd0[head] += c[nt][0] * ad0 + c[nt][1] * ad1;
        pd1[head] += c[nt][2] * ad0 + c[nt][3] * ad1;
    }
#pragma unroll
    for (int hd = 0; hd < 4; hd++) {
        ps0[hd] += __shfl_down_sync(0xFFFFFFFFu, ps0[hd], 1);
        ps0[hd] += __shfl_down_sync(0xFFFFFFFFu, ps0[hd], 2);
        ps1[hd] += __shfl_down_sync(0xFFFFFFFFu, ps1[hd], 1);
        ps1[hd] += __shfl_down_sync(0xFFFFFFFFu, ps1[hd], 2);
        pd0[hd] += __shfl_down_sync(0xFFFFFFFFu, pd0[hd], 1);
        pd0[hd] += __shfl_down_sync(0xFFFFFFFFu, pd0[hd], 2);
        pd1[hd] += __shfl_down_sync(0xFFFFFFFFu, pd1[hd], 1);
        pd1[hd] += __shfl_down_sync(0xFFFFFFFFu, pd1[hd], 2);
    }
    if (tq == 0) {
        if (r0 < Nn) {
#pragma unroll
            for (int hd = 0; hd < 4; hd++) {
                g_asrc[r0 * 4 + hd] = ps0[hd];
                g_adst[r0 * 4 + hd] = pd0[hd];
            }
        }
        if (r1 < Nn) {
#pragma unroll
            for (int hd = 0; hd < 4; hd++) {
                g_asrc[r1 * 4 + hd] = ps1[hd];
                g_adst[r1 * 4 + hd] = pd1[hd];
            }
        }
    }
}

// ---------------- bucket scatter ---------------------------------------------
__global__ void scatter_kernel(const int* __restrict__ ei) {
    int i4 = (blockIdx.x * blockDim.x + threadIdx.x) * 4;
    if (i4 >= Ee) return;
    int4 s4 = *(const int4*)&ei[i4];
    int4 d4 = *(const int4*)&ei[Ee + i4];
    int p0 = atomicAdd(&g_cur[d4.x], 1);
    int p1 = atomicAdd(&g_cur[d4.y], 1);
    int p2 = atomicAdd(&g_cur[d4.z], 1);
    int p3 = atomicAdd(&g_cur[d4.w], 1);
    if (p0 < CAP) g_csr[(size_t)d4.x * CAP + p0] = s4.x;
    if (p1 < CAP) g_csr[(size_t)d4.y * CAP + p1] = s4.y;
    if (p2 < CAP) g_csr[(size_t)d4.z * CAP + p2] = s4.z;
    if (p3 < CAP) g_csr[(size_t)d4.w * CAP + p3] = s4.w;
}

// ---------------- K6: gather-aggregate, occupancy-first ----------------------
// One warp per node, batch-4, MINIMAL register state, forced 4 blocks/SM
// (8 warps/SMSP) so cross-warp parallelism hides the bucket->gather latency.
__global__ __launch_bounds__(256, 4) void agg_kernel(const float* __restrict__ bias) {
    int lane = threadIdx.x & 31;
    int warp = (blockIdx.x * blockDim.x + threadIdx.x) >> 5;
    int nwarps = (gridDim.x * blockDim.x) >> 5;
    int hd = lane >> 3;

    __shared__ float sh_s[128];
    __shared__ float sh_q[128];
    if (threadIdx.x < 128) { sh_s[threadIdx.x] = 0.f; sh_q[threadIdx.x] = 0.f; }
    __syncthreads();

    float4 b = ((const float4*)bias)[lane];
    float bs_x = 0.f, bs_y = 0.f, bs_z = 0.f, bs_w = 0.f;
    float bq_x = 0.f, bq_y = 0.f, bq_z = 0.f, bq_w = 0.f;

#pragma unroll 1
    for (int w = warp; w < Nn; w += nwarps) {
        const float ad = __ldg(&g_adst[w * 4 + hd]);
        float4 acc = make_float4(0.f, 0.f, 0.f, 0.f);
        float den = 0.f;

        // self loop
        {
            float e = __ldg(&g_asrc[w * 4 + hd]) + ad;
            e = fmaxf(e, NEG * e);
            float ex = __expf(e);
            uint2 raw = *(const uint2*)&g_h16[(size_t)w * 128 + lane * 4];
            float2 f0 = __half22float2(*(__half2*)&raw.x);
            float2 f1 = __half22float2(*(__half2*)&raw.y);
            acc.x += ex * f0.x; acc.y += ex * f0.y;
            acc.z += ex * f1.x; acc.w += ex * f1.y;
            den += ex;
        }

        int len = min(g_cur[w], CAP);
        const int4* bkt = (const int4*)&g_csr[(size_t)w * CAP];
#pragma unroll 1
        for (int j = 0; j < len; j += 4) {
            int4 iv = __ldg(&bkt[j >> 2]);       // always in-bounds (j < CAP)
            int s0 = (j + 0 < len) ? iv.x : w;   // clamp garbage slots
            int s1 = (j + 1 < len) ? iv.y : w;
            int s2 = (j + 2 < len) ? iv.z : w;
            int s3 = (j + 3 < len) ? iv.w : w;
            uint2 r0 = *(const uint2*)&g_h16[(size_t)s0 * 128 + lane * 4];
            uint2 r1 = *(const uint2*)&g_h16[(size_t)s1 * 128 + lane * 4];
            uint2 r2 = *(const uint2*)&g_h16[(size_t)s2 * 128 + lane * 4];
            uint2 r3 = *(const uint2*)&g_h16[(size_t)s3 * 128 + lane * 4];
            float e0 = __ldg(&g_asrc[s0 * 4 + hd]) + ad;
            float e1 = __ldg(&g_asrc[s1 * 4 + hd]) + ad;
            float e2 = __ldg(&g_asrc[s2 * 4 + hd]) + ad;
            float e3 = __ldg(&g_asrc[s3 * 4 + hd]) + ad;
            e0 = fmaxf(e0, NEG * e0);
            e1 = fmaxf(e1, NEG * e1);
            e2 = fmaxf(e2, NEG * e2);
            e3 = fmaxf(e3, NEG * e3);
            float x0 = (j + 0 < len) ? __expf(e0) : 0.f;
            float x1 = (j + 1 < len) ? __expf(e1) : 0.f;
            float x2 = (j + 2 < len) ? __expf(e2) : 0.f;
            float x3 = (j + 3 < len) ? __expf(e3) : 0.f;
            float2 f;
            f = __half22float2(*(__half2*)&r0.x); acc.x += x0 * f.x; acc.y += x0 * f.y;
            f = __half22float2(*(__half2*)&r0.y); acc.z += x0 * f.x; acc.w += x0 * f.y;
            f = __half22float2(*(__half2*)&r1.x); acc.x += x1 * f.x; acc.y += x1 * f.y;
            f = __half22float2(*(__half2*)&r1.y); acc.z += x1 * f.x; acc.w += x1 * f.y;
            f = __half22float2(*(__half2*)&r2.x); acc.x += x2 * f.x; acc.y += x2 * f.y;
            f = __half22float2(*(__half2*)&r2.y); acc.z += x2 * f.x; acc.w += x2 * f.y;
            f = __half22float2(*(__half2*)&r3.x); acc.x += x3 * f.x; acc.y += x3 * f.y;
            f = __half22float2(*(__half2*)&r3.y); acc.z += x3 * f.x; acc.w += x3 * f.y;
            den += x0 + x1 + x2 + x3;
        }

        float rden = 1.f / (den + 1e-16f);
        float4 o;
        o.x = fmaxf(acc.x * rden + b.x, 0.f);
        o.y = fmaxf(acc.y * rden + b.y, 0.f);
        o.z = fmaxf(acc.z * rden + b.z, 0.f);
        o.w = fmaxf(acc.w * rden + b.w, 0.f);
        ((float4*)g_agg)[(size_t)w * 32 + lane] = o;

        bs_x += o.x; bs_y += o.y; bs_z += o.z; bs_w += o.w;
        bq_x += o.x * o.x; bq_y += o.y * o.y; bq_z += o.z * o.z; bq_w += o.w * o.w;
    }

    atomicAdd(&sh_s[lane * 4 + 0], bs_x);
    atomicAdd(&sh_s[lane * 4 + 1], bs_y);
    atomicAdd(&sh_s[lane * 4 + 2], bs_z);
    atomicAdd(&sh_s[lane * 4 + 3], bs_w);
    atomicAdd(&sh_q[lane * 4 + 0], bq_x);
    atomicAdd(&sh_q[lane * 4 + 1], bq_y);
    atomicAdd(&sh_q[lane * 4 + 2], bq_z);
    atomicAdd(&sh_q[lane * 4 + 3], bq_w);
    __syncthreads();
    if (threadIdx.x < 128) atomicAdd(&g_bns[threadIdx.x], sh_s[threadIdx.x]);
    else if (threadIdx.x < 256) atomicAdd(&g_bnq[threadIdx.x - 128], sh_q[threadIdx.x - 128]);
}

// ---------------- K8: BN normalize + write output ----------------------------
__global__ void bn_apply_kernel(const float* __restrict__ gamma,
                                const float* __restrict__ beta,
                                float* __restrict__ out) {
    int i = (blockIdx.x * blockDim.x + threadIdx.x) * 4;
    if (i >= Nn * 128) return;
    int f = i & 127;
    const float invn = 1.f / (float)Nn;
    float4 v = *(const float4*)&g_agg[i];
    float4 s = *(const float4*)&g_bns[f];
    float4 q = *(const float4*)&g_bnq[f];
    float4 gm = *(const float4*)&gamma[f];
    float4 bt = *(const float4*)&beta[f];
    float m0 = s.x * invn, m1 = s.y * invn, m2 = s.z * invn, m3 = s.w * invn;
    float4 o;
    o.x = (v.x - m0) * rsqrtf(q.x * invn - m0 * m0 + BN_EPS) * gm.x + bt.x;
    o.y = (v.y - m1) * rsqrtf(q.y * invn - m1 * m1 + BN_EPS) * gm.y + bt.y;
    o.z = (v.z - m2) * rsqrtf(q.z * invn - m2 * m2 + BN_EPS) * gm.z + bt.z;
    o.w = (v.w - m3) * rsqrtf(q.w * invn - m3 * m3 + BN_EPS) * gm.w + bt.w;
    *(float4*)&out[i] = o;
}

// ---------------- launch ------------------------------------------------------
extern "C" void kernel_launch(void* const* d_in, const int* in_sizes, int n_in,
                              void* d_out, int out_size) {
    (void)in_sizes; (void)n_in; (void)out_size;
    const float* x       = (const float*)d_in[0];
    const int*   ei      = (const int*)d_in[1];
    const float* W       = (const float*)d_in[2];
    const float* att_src = (const float*)d_in[3];
    const float* att_dst = (const float*)d_in[4];
    const float* bias    = (const float*)d_in[5];
    const float* gamma   = (const float*)d_in[6];
    const float* beta    = (const float*)d_in[7];

    cudaStream_t s2;
    cudaStreamCreateWithFlags(&s2, cudaStreamNonBlocking);
    cudaEvent_t eFork, eJoin;
    cudaEventCreateWithFlags(&eFork, cudaEventDisableTiming);
    cudaEventCreateWithFlags(&eJoin, cudaEventDisableTiming);

    cudaEventRecord(eFork, 0);
    cudaStreamWaitEvent(s2, eFork, 0);

    void* p;
    // side branch (stream s2) — hidden under the GEMM
    cudaGetSymbolAddress(&p, g_cur);  cudaMemsetAsync(p, 0, sizeof(int) * Nn, s2);
    cudaGetSymbolAddress(&p, g_bns);  cudaMemsetAsync(p, 0, sizeof(float) * Ff, s2);
    cudaGetSymbolAddress(&p, g_bnq);  cudaMemsetAsync(p, 0, sizeof(float) * Ff, s2);
    scatter_kernel<<<(Ee / 4 + 255) / 256, 256, 0, s2>>>(ei);

    // main branch (stream 0): pure compute
    gemm_att_kernel<<<(Nn + 127) / 128, 256>>>(x, W, att_src, att_dst);

    cudaEventRecord(eJoin, s2);
    cudaStreamWaitEvent(0, eJoin, 0);

    agg_kernel<<<592, 256>>>(bias);
    bn_apply_kernel<<<(Nn * 128 / 4 + 255) / 256, 256>>>(gamma, beta, (float*)d_out);

    cudaStreamDestroy(s2);
    cudaEventDestroy(eFork);
    cudaEventDestroy(eJoin);
}